// round 2
// baseline (speedup 1.0000x reference)
#include <cuda_runtime.h>
#include <cuda_bf16.h>
#include <math.h>

// ---------------------------------------------------------------------------
// Problem constants
// ---------------------------------------------------------------------------
#define BATCH   16384
#define LSEQ    200
#define SDIM    64
#define CONCAT  244
#define NEXP    8
#define EHID    256
#define EOUT    128
#define NTASK   2
#define CHUNK   32     // history positions processed per smem chunk

// ---------------------------------------------------------------------------
// Scratch (static device globals — no allocation allowed)
// ---------------------------------------------------------------------------
__device__ float g_S [(long)BATCH * CONCAT];            // shared feature rows (16 MB)
__device__ float g_eh[(long)NEXP * BATCH * EHID];       // expert hidden (134 MB)
__device__ float g_eo[(long)NEXP * BATCH * EOUT];       // expert out (67 MB)

// ---------------------------------------------------------------------------
// Kernel 1: DIN attention + pooling + feature concat
// One block per batch row. 256 threads (8 warps).
// Layer-1 trick: h1 = relu(base + h @ M) with per-row M (64x64):
//   feat = [t, h, t-h, t*h];  feat @ aW1
//     = t@(W[0:64]+W[128:192]) + h@(W[64:128]-W[128:192]+diag(t)W[192:256])
// Static smem (< 48 KB) so no cudaFuncSetAttribute is needed.
// ---------------------------------------------------------------------------
struct AttnSmem {
    float M[64 * 64];          // per-row combined layer1 matrix  (16 KB)
    float hc[CHUNK * 64];      // gathered history chunk           (8 KB)
    float h1[CHUNK * 65];      // layer1 activations (padded)      (8.3 KB)
    float tvec[64];
    float base[64];
    float ibuf[64];
    float aW2s[64 * 16];       // (4 KB)
    float aW3s[16];
    float ab2s[16];
    int   seqs[LSEQ];
    float scores[LSEQ];
    float attn[LSEQ];
    float red[32];
    float pool[4][64];
    float poolred[64];
};

__global__ void __launch_bounds__(256)
attn_kernel(const int* __restrict__ uid, const int* __restrict__ iid,
            const int* __restrict__ cid, const int* __restrict__ did,
            const float* __restrict__ udense, const float* __restrict__ idense,
            const int* __restrict__ hseq,
            const float* __restrict__ userE, const float* __restrict__ itemE,
            const float* __restrict__ catE,  const float* __restrict__ durE,
            const float* __restrict__ histE, const float* __restrict__ Wproj,
            const float* __restrict__ aW1, const float* __restrict__ ab1,
            const float* __restrict__ aW2, const float* __restrict__ ab2,
            const float* __restrict__ aW3, const float* __restrict__ ab3,
            float* __restrict__ Sout)
{
    __shared__ AttnSmem s;

    const int b    = blockIdx.x;
    const int tid  = threadIdx.x;
    const int lane = tid & 31;
    const int warp = tid >> 5;

    // ---- stage small constants + item embedding + sequence ids ----
    const int item = iid[b];
    if (tid < 64) s.ibuf[tid] = itemE[(long)item * 64 + tid];
    for (int i = tid; i < 64 * 16; i += 256) s.aW2s[i] = aW2[i];
    if (tid < 16) { s.aW3s[tid] = aW3[tid]; s.ab2s[tid] = ab2[tid]; }
    for (int l = tid; l < LSEQ; l += 256) s.seqs[l] = hseq[(long)b * LSEQ + l];
    __syncthreads();

    // ---- t = i_emb @ Wproj  (64x64 matvec) ----
    if (tid < 64) {
        float acc = 0.f;
        #pragma unroll 4
        for (int k = 0; k < 64; k++) acc += s.ibuf[k] * Wproj[k * 64 + tid];
        s.tvec[tid] = acc;
    }
    __syncthreads();

    // ---- base[j] = ab1 + t @ (aW1[0:64] + aW1[128:192]) ----
    if (tid < 64) {
        float acc = ab1[tid];
        #pragma unroll 4
        for (int k = 0; k < 64; k++)
            acc += s.tvec[k] * (aW1[k * 64 + tid] + aW1[(128 + k) * 64 + tid]);
        s.base[tid] = acc;
    }
    // ---- M[k][j] = aW1[64+k][j] - aW1[128+k][j] + t[k]*aW1[192+k][j] ----
    for (int idx = tid; idx < 64 * 64; idx += 256) {
        int k = idx >> 6, j = idx & 63;
        s.M[idx] = aW1[(64 + k) * 64 + j] - aW1[(128 + k) * 64 + j]
                 + s.tvec[k] * aW1[(192 + k) * 64 + j];
    }
    __syncthreads();

    const float ab3v = ab3[0];

    // ---- process history in chunks of CHUNK positions ----
    for (int c0 = 0; c0 < LSEQ; c0 += CHUNK) {
        // gather this chunk of history embeddings (histE is L2-resident)
        {
            const int d = tid & 63, g = tid >> 6;
            for (int pl = g; pl < CHUNK; pl += 4) {
                const int l = c0 + pl;
                float v = 0.f;
                if (l < LSEQ) v = histE[(long)s.seqs[l] * 64 + d];
                s.hc[pl * 64 + d] = v;
            }
        }
        __syncthreads();

        // each warp handles 4 positions: 8 warps * 4 = 32 positions = CHUNK
        {
            const int pbase = warp * 4;

            // layer 1: h1 = relu(base + h @ M), 2 outputs/lane, 4 pos/warp
            float acc[4][2];
            {
                const float b0 = s.base[lane], b1 = s.base[lane + 32];
                #pragma unroll
                for (int i = 0; i < 4; i++) { acc[i][0] = b0; acc[i][1] = b1; }
            }
            #pragma unroll 4
            for (int k = 0; k < 64; k++) {
                const float m0 = s.M[k * 64 + lane];
                const float m1 = s.M[k * 64 + lane + 32];
                #pragma unroll
                for (int i = 0; i < 4; i++) {
                    const float hk = s.hc[(pbase + i) * 64 + k];
                    acc[i][0] += hk * m0;
                    acc[i][1] += hk * m1;
                }
            }
            #pragma unroll
            for (int i = 0; i < 4; i++) {
                s.h1[(pbase + i) * 65 + lane]      = fmaxf(acc[i][0], 0.f);
                s.h1[(pbase + i) * 65 + lane + 32] = fmaxf(acc[i][1], 0.f);
            }
            __syncwarp();

            // layers 2+3: two positions per pass (half-warp each)
            #pragma unroll
            for (int q = 0; q < 2; q++) {
                const int p = pbase + q * 2 + (lane >> 4);
                const int m = lane & 15;
                float a2 = s.ab2s[m];
                #pragma unroll 4
                for (int j = 0; j < 64; j++)
                    a2 += s.h1[p * 65 + j] * s.aW2s[j * 16 + m];
                float val = fmaxf(a2, 0.f) * s.aW3s[m];
                #pragma unroll
                for (int off = 8; off >= 1; off >>= 1)
                    val += __shfl_xor_sync(0xffffffffu, val, off, 16);
                if (m == 0) {
                    const int l = c0 + p;
                    if (l < LSEQ) {
                        const float sc = val + ab3v;
                        s.scores[l] = (s.seqs[l] == 0) ? -1e9f : sc;
                    }
                }
            }
        }
        __syncthreads();
    }

    // ---- softmax over L (LSEQ=200 <= 256 threads) ----
    float sv = (tid < LSEQ) ? s.scores[tid] : -3.4e38f;
    {
        float m = sv;
        #pragma unroll
        for (int off = 16; off >= 1; off >>= 1)
            m = fmaxf(m, __shfl_xor_sync(0xffffffffu, m, off));
        if (lane == 0) s.red[warp] = m;
    }
    __syncthreads();
    if (tid == 0) {
        float mm = s.red[0];
        for (int w = 1; w < 8; w++) mm = fmaxf(mm, s.red[w]);
        s.red[16] = mm;
    }
    __syncthreads();
    const float smax = s.red[16];
    float e = (tid < LSEQ) ? __expf(sv - smax) : 0.f;
    if (tid < LSEQ) s.attn[tid] = e;
    {
        float sum = e;
        #pragma unroll
        for (int off = 16; off >= 1; off >>= 1)
            sum += __shfl_xor_sync(0xffffffffu, sum, off);
        if (lane == 0) s.red[warp] = sum;
    }
    __syncthreads();
    if (tid == 0) {
        float ss = 0.f;
        for (int w = 0; w < 8; w++) ss += s.red[w];
        s.red[17] = 1.f / ss;
    }
    __syncthreads();
    const float inv = s.red[17];
    if (tid < LSEQ) s.attn[tid] *= inv;
    __syncthreads();

    // ---- pooled = attn @ h  (re-gather history, L2-resident) ----
    {
        const int d = tid & 63, g = tid >> 6;
        float acc = 0.f;
        for (int l = g; l < LSEQ; l += 4)
            acc += s.attn[l] * histE[(long)s.seqs[l] * 64 + d];
        s.pool[g][d] = acc;
    }
    __syncthreads();
    if (tid < 64)
        s.poolred[tid] = s.pool[0][tid] + s.pool[1][tid] + s.pool[2][tid] + s.pool[3][tid];
    __syncthreads();

    // ---- write shared feature row: [u(64) i(64) c(16) d(8) ud(25) idn(3) pooled(64)] ----
    if (tid < CONCAT) {
        float v;
        if      (tid < 64)  v = userE[(long)uid[b] * 64 + tid];
        else if (tid < 128) v = s.ibuf[tid - 64];
        else if (tid < 144) v = catE[(long)cid[b] * 16 + (tid - 128)];
        else if (tid < 152) v = durE[(long)did[b] * 8 + (tid - 144)];
        else if (tid < 177) v = udense[(long)b * 25 + (tid - 152)];
        else if (tid < 180) v = idense[(long)b * 3 + (tid - 177)];
        else                v = s.poolred[tid - 180];
        Sout[(long)b * CONCAT + tid] = v;
    }
}

// ---------------------------------------------------------------------------
// Kernel 2: batched SGEMM + bias + ReLU
// C[z] = relu(A[z] (MxK) @ B[z] (KxN) + bias[z])
// BM=BN=128, BK=8, 256 threads, 8x8 register tiles.
// ---------------------------------------------------------------------------
__global__ void __launch_bounds__(256)
sgemm_bias_relu(const float* __restrict__ A, const float* __restrict__ Bw,
                const float* __restrict__ bias, float* __restrict__ C,
                int M, int N, int K,
                size_t sA, size_t sB, size_t sBias, size_t sC)
{
    const int BM = 128, BN = 128, BK = 8;
    __shared__ float As[BK][BM];
    __shared__ float Bs[BK][BN];

    const int z = blockIdx.z;
    A += (size_t)z * sA; Bw += (size_t)z * sB;
    bias += (size_t)z * sBias; C += (size_t)z * sC;

    const int m0 = blockIdx.y * BM;
    const int n0 = blockIdx.x * BN;
    const int tid = threadIdx.x;
    const int ty = tid >> 4, tx = tid & 15;
    const int ry = ty * 8, cx = tx * 8;

    const int arow = tid >> 1, ac4 = (tid & 1) * 4;
    const int brow = tid >> 5, bcol = (tid & 31) * 4;

    float acc[8][8];
    #pragma unroll
    for (int i = 0; i < 8; i++)
        #pragma unroll
        for (int j = 0; j < 8; j++) acc[i][j] = 0.f;

    for (int k0 = 0; k0 < K; k0 += BK) {
        // load A tile (transposed into smem)
        {
            const float* ap = A + (size_t)(m0 + arow) * K + k0 + ac4;
            if (k0 + ac4 + 3 < K) {
                float4 v = *reinterpret_cast<const float4*>(ap);
                As[ac4 + 0][arow] = v.x; As[ac4 + 1][arow] = v.y;
                As[ac4 + 2][arow] = v.z; As[ac4 + 3][arow] = v.w;
            } else {
                #pragma unroll
                for (int j = 0; j < 4; j++)
                    As[ac4 + j][arow] = (k0 + ac4 + j < K) ? ap[j] : 0.f;
            }
        }
        // load B tile
        {
            const int k = k0 + brow;
            float4 v = make_float4(0.f, 0.f, 0.f, 0.f);
            if (k < K)
                v = *reinterpret_cast<const float4*>(Bw + (size_t)k * N + n0 + bcol);
            *reinterpret_cast<float4*>(&Bs[brow][bcol]) = v;
        }
        __syncthreads();

        #pragma unroll
        for (int kk = 0; kk < BK; kk++) {
            float4 a0 = *reinterpret_cast<const float4*>(&As[kk][ry]);
            float4 a1 = *reinterpret_cast<const float4*>(&As[kk][ry + 4]);
            float4 b0 = *reinterpret_cast<const float4*>(&Bs[kk][cx]);
            float4 b1 = *reinterpret_cast<const float4*>(&Bs[kk][cx + 4]);
            float ar[8] = {a0.x, a0.y, a0.z, a0.w, a1.x, a1.y, a1.z, a1.w};
            float br[8] = {b0.x, b0.y, b0.z, b0.w, b1.x, b1.y, b1.z, b1.w};
            #pragma unroll
            for (int i = 0; i < 8; i++)
                #pragma unroll
                for (int j = 0; j < 8; j++)
                    acc[i][j] += ar[i] * br[j];
        }
        __syncthreads();
    }

    // epilogue: bias + relu
    #pragma unroll
    for (int i = 0; i < 8; i++) {
        float* cp = C + (size_t)(m0 + ry + i) * N + n0 + cx;
        #pragma unroll
        for (int j = 0; j < 8; j++)
            cp[j] = fmaxf(acc[i][j] + bias[n0 + cx + j], 0.f);
    }
}

// ---------------------------------------------------------------------------
// Kernel 3: gates (softmax) + expert mix + towers + sigmoid
// 256 threads = 4 groups of 64 lanes; one batch row per group.
// ---------------------------------------------------------------------------
__global__ void __launch_bounds__(256)
head_kernel(const float* __restrict__ S, const float* __restrict__ eo,
            const float* __restrict__ gW, const float* __restrict__ gb,
            const float* __restrict__ tW1, const float* __restrict__ tb1,
            const float* __restrict__ tW2, const float* __restrict__ tb2,
            const float* __restrict__ tW3, const float* __restrict__ tb3,
            float* __restrict__ out)
{
    __shared__ float Srow[4][CONCAT];
    __shared__ float gate[4][16];
    __shared__ float ti[4][NTASK][EOUT];
    __shared__ float x1[4][NTASK][64];
    __shared__ float x2[4][NTASK][32];

    const int g = threadIdx.x >> 6;
    const int lane = threadIdx.x & 63;
    const int b = blockIdx.x * 4 + g;

    for (int c = lane; c < CONCAT; c += 64) Srow[g][c] = S[(long)b * CONCAT + c];
    __syncthreads();

    // gate logits
    if (lane < 16) {
        const int t = lane >> 3, e = lane & 7;
        float acc = gb[t * 8 + e];
        for (int c = 0; c < CONCAT; c++)
            acc += Srow[g][c] * gW[((long)t * CONCAT + c) * 8 + e];
        gate[g][lane] = acc;
    }
    __syncthreads();
    // softmax over experts
    if (lane < 2) {
        const int t = lane;
        float mx = -3.4e38f;
        for (int e = 0; e < 8; e++) mx = fmaxf(mx, gate[g][t * 8 + e]);
        float sum = 0.f, ex[8];
        for (int e = 0; e < 8; e++) { ex[e] = __expf(gate[g][t * 8 + e] - mx); sum += ex[e]; }
        const float is = 1.f / sum;
        for (int e = 0; e < 8; e++) gate[g][t * 8 + e] = ex[e] * is;
    }
    __syncthreads();

    // mix experts: ti[t][o] = sum_e gate[t][e] * eo[e][b][o]
    for (int idx = lane; idx < NTASK * EOUT; idx += 64) {
        const int t = idx >> 7, o = idx & 127;
        float acc = 0.f;
        #pragma unroll
        for (int e = 0; e < 8; e++)
            acc += gate[g][t * 8 + e] * eo[((long)e * BATCH + b) * EOUT + o];
        ti[g][t][o] = acc;
    }
    __syncthreads();

    // tower layer 1: 128 -> 64
    for (int idx = lane; idx < NTASK * 64; idx += 64) {
        const int t = idx >> 6, j = idx & 63;
        float acc = tb1[t * 64 + j];
        #pragma unroll 4
        for (int o = 0; o < 128; o++)
            acc += ti[g][t][o] * tW1[((long)t * 128 + o) * 64 + j];
        x1[g][t][j] = fmaxf(acc, 0.f);
    }
    __syncthreads();

    // tower layer 2: 64 -> 32
    {
        const int t = lane >> 5, m = lane & 31;
        float acc = tb2[t * 32 + m];
        #pragma unroll 4
        for (int j = 0; j < 64; j++)
            acc += x1[g][t][j] * tW2[(t * 64 + j) * 32 + m];
        x2[g][t][m] = fmaxf(acc, 0.f);
    }
    __syncthreads();

    // tower layer 3 + sigmoid
    if (lane < 2) {
        const int t = lane;
        float acc = tb3[t];
        #pragma unroll
        for (int m = 0; m < 32; m++) acc += x2[g][t][m] * tW3[t * 32 + m];
        out[(long)t * BATCH + b] = 1.f / (1.f + __expf(-acc));
    }
}

// ---------------------------------------------------------------------------
// Launch
// ---------------------------------------------------------------------------
extern "C" void kernel_launch(void* const* d_in, const int* in_sizes, int n_in,
                              void* d_out, int out_size)
{
    const int*   uid    = (const int*)  d_in[0];
    const int*   iid    = (const int*)  d_in[1];
    const int*   cid    = (const int*)  d_in[2];
    const int*   did    = (const int*)  d_in[3];
    const float* udense = (const float*)d_in[4];
    const float* idense = (const float*)d_in[5];
    const int*   hseq   = (const int*)  d_in[6];
    const float* userE  = (const float*)d_in[7];
    const float* itemE  = (const float*)d_in[8];
    const float* catE   = (const float*)d_in[9];
    const float* durE   = (const float*)d_in[10];
    const float* histE  = (const float*)d_in[11];
    const float* Wproj  = (const float*)d_in[12];
    const float* aW1    = (const float*)d_in[13];
    const float* ab1    = (const float*)d_in[14];
    const float* aW2    = (const float*)d_in[15];
    const float* ab2    = (const float*)d_in[16];
    const float* aW3    = (const float*)d_in[17];
    const float* ab3    = (const float*)d_in[18];
    const float* eW1    = (const float*)d_in[19];
    const float* eb1    = (const float*)d_in[20];
    const float* eW2    = (const float*)d_in[21];
    const float* eb2    = (const float*)d_in[22];
    const float* gW     = (const float*)d_in[23];
    const float* gb     = (const float*)d_in[24];
    const float* tW1    = (const float*)d_in[25];
    const float* tb1    = (const float*)d_in[26];
    const float* tW2    = (const float*)d_in[27];
    const float* tb2    = (const float*)d_in[28];
    const float* tW3    = (const float*)d_in[29];
    const float* tb3    = (const float*)d_in[30];
    float* out = (float*)d_out;

    float *pS, *pEh, *pEo;
    cudaGetSymbolAddress((void**)&pS,  g_S);
    cudaGetSymbolAddress((void**)&pEh, g_eh);
    cudaGetSymbolAddress((void**)&pEo, g_eo);

    // K1: attention + feature concat
    attn_kernel<<<BATCH, 256>>>(
        uid, iid, cid, did, udense, idense, hseq,
        userE, itemE, catE, durE, histE, Wproj,
        aW1, ab1, aW2, ab2, aW3, ab3, pS);

    // K2a: eh = relu(S @ eW1 + eb1)  per expert
    sgemm_bias_relu<<<dim3(EHID / 128, BATCH / 128, NEXP), 256>>>(
        pS, eW1, eb1, pEh,
        BATCH, EHID, CONCAT,
        (size_t)0, (size_t)CONCAT * EHID, (size_t)EHID, (size_t)BATCH * EHID);

    // K2b: eo = relu(eh @ eW2 + eb2)  per expert
    sgemm_bias_relu<<<dim3(EOUT / 128, BATCH / 128, NEXP), 256>>>(
        pEh, eW2, eb2, pEo,
        BATCH, EOUT, EHID,
        (size_t)BATCH * EHID, (size_t)EHID * EOUT, (size_t)EOUT, (size_t)BATCH * EOUT);

    // K3: gates + mix + towers + sigmoid
    head_kernel<<<BATCH / 4, 256>>>(
        pS, pEo, gW, gb, tW1, tb1, tW2, tb2, tW3, tb3, out);
}

// round 3
// speedup vs baseline: 1.2509x; 1.2509x over previous
#include <cuda_runtime.h>
#include <cuda_bf16.h>
#include <mma.h>
#include <math.h>

using namespace nvcuda;

// ---------------------------------------------------------------------------
// Problem constants
// ---------------------------------------------------------------------------
#define BATCH   16384
#define LSEQ    200
#define SDIM    64
#define CONCAT  244
#define NEXP    8
#define EHID    256
#define EOUT    128
#define NTASK   2
#define CHUNK   32     // history positions per chunk (2 x m16 tiles)
#define HLD     72     // padded leading dim for hc/h1 (mult of 8)

// ---------------------------------------------------------------------------
// Scratch (static device globals — no allocation allowed)
// ---------------------------------------------------------------------------
__device__ float g_S [(long)BATCH * CONCAT];            // shared feature rows (16 MB)
__device__ float g_eh[(long)NEXP * BATCH * EHID];       // expert hidden (134 MB)
__device__ float g_eo[(long)NEXP * BATCH * EOUT];       // expert out (67 MB)

// ---------------------------------------------------------------------------
// Kernel 1: DIN attention + pooling + feature concat (tf32 WMMA inner GEMMs)
// One block per batch row, 256 threads (8 warps).
//   feat@aW1 = base + h @ M   with per-row M[k][j] =
//       aW1[64+k][j] - aW1[128+k][j] + t[k]*aW1[192+k][j]
// ---------------------------------------------------------------------------
struct AttnSmem {
    float M[64 * 64];            // layer1 combined matrix (k x j, row-major)
    float hc[CHUNK * HLD];       // gathered history chunk
    float h1[CHUNK * HLD];       // layer1 activations
    float h2[CHUNK * 16];        // layer2 pre-activations
    float tvec[64];
    float base[64];
    float ibuf[64];
    float aW2s[64 * 16];         // row-major k x 16
    float aW3s[16];
    float ab2s[16];
    int   seqs[LSEQ];
    float scores[LSEQ];
    float attn[LSEQ];
    float red[32];
    float pool[4][64];
    float poolred[64];
};

__global__ void __launch_bounds__(256)
attn_kernel(const int* __restrict__ uid, const int* __restrict__ iid,
            const int* __restrict__ cid, const int* __restrict__ did,
            const float* __restrict__ udense, const float* __restrict__ idense,
            const int* __restrict__ hseq,
            const float* __restrict__ userE, const float* __restrict__ itemE,
            const float* __restrict__ catE,  const float* __restrict__ durE,
            const float* __restrict__ histE, const float* __restrict__ Wproj,
            const float* __restrict__ aW1, const float* __restrict__ ab1,
            const float* __restrict__ aW2, const float* __restrict__ ab2,
            const float* __restrict__ aW3, const float* __restrict__ ab3,
            float* __restrict__ Sout)
{
    __shared__ AttnSmem s;

    const int b    = blockIdx.x;
    const int tid  = threadIdx.x;
    const int lane = tid & 31;
    const int warp = tid >> 5;

    // ---- stage constants + item embedding + sequence ids ----
    const int item = iid[b];
    if (tid < 64) s.ibuf[tid] = itemE[(long)item * 64 + tid];
    for (int i = tid; i < 64 * 16; i += 256) s.aW2s[i] = aW2[i];
    if (tid < 16) { s.aW3s[tid] = aW3[tid]; s.ab2s[tid] = ab2[tid]; }
    for (int l = tid; l < LSEQ; l += 256) s.seqs[l] = hseq[(long)b * LSEQ + l];
    __syncthreads();

    // ---- t = i_emb @ Wproj ----
    if (tid < 64) {
        float acc = 0.f;
        #pragma unroll 4
        for (int k = 0; k < 64; k++) acc += s.ibuf[k] * Wproj[k * 64 + tid];
        s.tvec[tid] = acc;
    }
    __syncthreads();

    // ---- base / M ----
    if (tid < 64) {
        float acc = ab1[tid];
        #pragma unroll 4
        for (int k = 0; k < 64; k++)
            acc += s.tvec[k] * (aW1[k * 64 + tid] + aW1[(128 + k) * 64 + tid]);
        s.base[tid] = acc;
    }
    for (int idx = tid; idx < 64 * 64; idx += 256) {
        int k = idx >> 6, j = idx & 63;
        s.M[idx] = aW1[(64 + k) * 64 + j] - aW1[(128 + k) * 64 + j]
                 + s.tvec[k] * aW1[(192 + k) * 64 + j];
    }
    __syncthreads();

    const float ab3v = ab3[0];

    // ---- chunk loop ----
    for (int c0 = 0; c0 < LSEQ; c0 += CHUNK) {
        // gather chunk (float4, coalesced; histE is L2-resident)
        {
            const int pr = tid >> 4;            // 0..15
            const int c4 = (tid & 15) * 4;      // 0..60
            #pragma unroll
            for (int h = 0; h < 2; h++) {
                const int pl = pr + h * 16;
                const int l = c0 + pl;
                float4 v = make_float4(0.f, 0.f, 0.f, 0.f);
                if (l < LSEQ)
                    v = *reinterpret_cast<const float4*>(histE + (long)s.seqs[l] * 64 + c4);
                *reinterpret_cast<float4*>(&s.hc[pl * HLD + c4]) = v;
            }
        }
        __syncthreads();

        // layer 1: h1(32x64) = hc(32x64) @ M(64x64) via tf32 wmma
        {
            const int rt = warp >> 2;           // row tile 0..1
            const int ct = warp & 3;            // col tile 0..3
            wmma::fragment<wmma::accumulator, 16, 16, 8, float> accf;
            wmma::fill_fragment(accf, 0.f);
            #pragma unroll
            for (int ks = 0; ks < 8; ks++) {
                wmma::fragment<wmma::matrix_a, 16, 16, 8, wmma::precision::tf32, wmma::row_major> af;
                wmma::fragment<wmma::matrix_b, 16, 16, 8, wmma::precision::tf32, wmma::row_major> bf;
                wmma::load_matrix_sync(af, &s.hc[(rt * 16) * HLD + ks * 8], HLD);
                wmma::load_matrix_sync(bf, &s.M[(ks * 8) * 64 + ct * 16], 64);
                #pragma unroll
                for (int i = 0; i < af.num_elements; i++) af.x[i] = wmma::__float_to_tf32(af.x[i]);
                #pragma unroll
                for (int i = 0; i < bf.num_elements; i++) bf.x[i] = wmma::__float_to_tf32(bf.x[i]);
                wmma::mma_sync(accf, af, bf, accf);
            }
            wmma::store_matrix_sync(&s.h1[(rt * 16) * HLD + ct * 16], accf, HLD, wmma::mem_row_major);
        }
        __syncthreads();

        // bias + relu on h1
        for (int idx = tid; idx < CHUNK * 64; idx += 256) {
            const int p = idx >> 6, j = idx & 63;
            s.h1[p * HLD + j] = fmaxf(s.h1[p * HLD + j] + s.base[j], 0.f);
        }
        __syncthreads();

        // layer 2: h2(32x16) = h1(32x64) @ aW2(64x16) via wmma (warps 0,1)
        if (warp < 2) {
            wmma::fragment<wmma::accumulator, 16, 16, 8, float> accf;
            wmma::fill_fragment(accf, 0.f);
            #pragma unroll
            for (int ks = 0; ks < 8; ks++) {
                wmma::fragment<wmma::matrix_a, 16, 16, 8, wmma::precision::tf32, wmma::row_major> af;
                wmma::fragment<wmma::matrix_b, 16, 16, 8, wmma::precision::tf32, wmma::row_major> bf;
                wmma::load_matrix_sync(af, &s.h1[(warp * 16) * HLD + ks * 8], HLD);
                wmma::load_matrix_sync(bf, &s.aW2s[(ks * 8) * 16], 16);
                #pragma unroll
                for (int i = 0; i < af.num_elements; i++) af.x[i] = wmma::__float_to_tf32(af.x[i]);
                #pragma unroll
                for (int i = 0; i < bf.num_elements; i++) bf.x[i] = wmma::__float_to_tf32(bf.x[i]);
                wmma::mma_sync(accf, af, bf, accf);
            }
            wmma::store_matrix_sync(&s.h2[(warp * 16) * 16], accf, 16, wmma::mem_row_major);
        }
        __syncthreads();

        // layer 3 + mask: warp 0, one position per lane
        if (warp == 0) {
            const int p = lane;
            float val = 0.f;
            #pragma unroll
            for (int m = 0; m < 16; m++)
                val += fmaxf(s.h2[p * 16 + m] + s.ab2s[m], 0.f) * s.aW3s[m];
            const int l = c0 + p;
            if (l < LSEQ)
                s.scores[l] = (s.seqs[l] == 0) ? -1e9f : (val + ab3v);
        }
        __syncthreads();
    }

    // ---- softmax over L ----
    float sv = (tid < LSEQ) ? s.scores[tid] : -3.4e38f;
    {
        float m = sv;
        #pragma unroll
        for (int off = 16; off >= 1; off >>= 1)
            m = fmaxf(m, __shfl_xor_sync(0xffffffffu, m, off));
        if (lane == 0) s.red[warp] = m;
    }
    __syncthreads();
    if (tid == 0) {
        float mm = s.red[0];
        for (int w = 1; w < 8; w++) mm = fmaxf(mm, s.red[w]);
        s.red[16] = mm;
    }
    __syncthreads();
    const float smax = s.red[16];
    float e = (tid < LSEQ) ? __expf(sv - smax) : 0.f;
    if (tid < LSEQ) s.attn[tid] = e;
    {
        float sum = e;
        #pragma unroll
        for (int off = 16; off >= 1; off >>= 1)
            sum += __shfl_xor_sync(0xffffffffu, sum, off);
        if (lane == 0) s.red[warp] = sum;
    }
    __syncthreads();
    if (tid == 0) {
        float ss = 0.f;
        for (int w = 0; w < 8; w++) ss += s.red[w];
        s.red[17] = 1.f / ss;
    }
    __syncthreads();
    const float inv = s.red[17];
    if (tid < LSEQ) s.attn[tid] *= inv;
    __syncthreads();

    // ---- pooled = attn @ h (re-gather, L2-resident) ----
    {
        const int d = tid & 63, g = tid >> 6;
        float acc = 0.f;
        for (int l = g; l < LSEQ; l += 4)
            acc += s.attn[l] * histE[(long)s.seqs[l] * 64 + d];
        s.pool[g][d] = acc;
    }
    __syncthreads();
    if (tid < 64)
        s.poolred[tid] = s.pool[0][tid] + s.pool[1][tid] + s.pool[2][tid] + s.pool[3][tid];
    __syncthreads();

    // ---- write feature row ----
    if (tid < CONCAT) {
        float v;
        if      (tid < 64)  v = userE[(long)uid[b] * 64 + tid];
        else if (tid < 128) v = s.ibuf[tid - 64];
        else if (tid < 144) v = catE[(long)cid[b] * 16 + (tid - 128)];
        else if (tid < 152) v = durE[(long)did[b] * 8 + (tid - 144)];
        else if (tid < 177) v = udense[(long)b * 25 + (tid - 152)];
        else if (tid < 180) v = idense[(long)b * 3 + (tid - 177)];
        else                v = s.poolred[tid - 180];
        Sout[(long)b * CONCAT + tid] = v;
    }
}

// ---------------------------------------------------------------------------
// Kernel 2: batched tf32 WMMA GEMM + bias + ReLU
// C[z] = relu(A[z] (MxK) @ B[z] (KxN) + bias[z])
// Block tile 128x64, BK=32, 256 threads (8 warps, 4x2), warp tile 32x32.
// ---------------------------------------------------------------------------
#define GBM 128
#define GBN 64
#define GBK 32
#define ALD (GBK + 4)    // 36
#define BLD (GBN + 4)    // 68

__global__ void __launch_bounds__(256)
wgemm_bias_relu(const float* __restrict__ A, const float* __restrict__ Bw,
                const float* __restrict__ bias, float* __restrict__ C,
                int M, int N, int K,
                size_t sA, size_t sB, size_t sBias, size_t sC)
{
    __shared__ float As[GBM * ALD];      // m x k
    __shared__ float Bs[GBK * BLD];      // k x n
    __shared__ float ebuf[8][16 * 20];   // per-warp epilogue staging

    const int z = blockIdx.z;
    A += (size_t)z * sA; Bw += (size_t)z * sB;
    bias += (size_t)z * sBias; C += (size_t)z * sC;

    const int m0 = blockIdx.y * GBM;
    const int n0 = blockIdx.x * GBN;
    const int tid = threadIdx.x;
    const int lane = tid & 31;
    const int warp = tid >> 5;
    const int wr = warp >> 1;            // 0..3  (row of warp grid)
    const int wc = warp & 1;             // 0..1  (col of warp grid)

    wmma::fragment<wmma::accumulator, 16, 16, 8, float> acc[2][2];
    #pragma unroll
    for (int i = 0; i < 2; i++)
        #pragma unroll
        for (int j = 0; j < 2; j++) wmma::fill_fragment(acc[i][j], 0.f);

    for (int k0 = 0; k0 < K; k0 += GBK) {
        // load A tile: 128x32, 256 threads x 4 float4
        {
            const int row = tid >> 3;            // 0..31
            const int c4  = (tid & 7) * 4;       // 0..28
            #pragma unroll
            for (int h = 0; h < 4; h++) {
                const int m = row + h * 32;
                const int k = k0 + c4;
                float4 v = make_float4(0.f, 0.f, 0.f, 0.f);
                if (k + 3 < K)
                    v = *reinterpret_cast<const float4*>(A + (size_t)(m0 + m) * K + k);
                else {
                    if (k + 0 < K) v.x = A[(size_t)(m0 + m) * K + k + 0];
                    if (k + 1 < K) v.y = A[(size_t)(m0 + m) * K + k + 1];
                    if (k + 2 < K) v.z = A[(size_t)(m0 + m) * K + k + 2];
                    if (k + 3 < K) v.w = A[(size_t)(m0 + m) * K + k + 3];
                }
                As[m * ALD + c4 + 0] = v.x;
                As[m * ALD + c4 + 1] = v.y;
                As[m * ALD + c4 + 2] = v.z;
                As[m * ALD + c4 + 3] = v.w;
            }
        }
        // load B tile: 32x64, 256 threads x 2 float4
        {
            const int krow = tid >> 4;           // 0..15
            const int c4   = (tid & 15) * 4;     // 0..60
            #pragma unroll
            for (int h = 0; h < 2; h++) {
                const int k = k0 + krow + h * 16;
                float4 v = make_float4(0.f, 0.f, 0.f, 0.f);
                if (k < K)
                    v = *reinterpret_cast<const float4*>(Bw + (size_t)k * N + n0 + c4);
                *reinterpret_cast<float4*>(&Bs[(krow + h * 16) * BLD + c4]) = v;
            }
        }
        __syncthreads();

        #pragma unroll
        for (int ks = 0; ks < GBK / 8; ks++) {
            wmma::fragment<wmma::matrix_a, 16, 16, 8, wmma::precision::tf32, wmma::row_major> af[2];
            wmma::fragment<wmma::matrix_b, 16, 16, 8, wmma::precision::tf32, wmma::row_major> bf[2];
            #pragma unroll
            for (int i = 0; i < 2; i++) {
                wmma::load_matrix_sync(af[i], &As[(wr * 32 + i * 16) * ALD + ks * 8], ALD);
                #pragma unroll
                for (int e = 0; e < af[i].num_elements; e++) af[i].x[e] = wmma::__float_to_tf32(af[i].x[e]);
            }
            #pragma unroll
            for (int j = 0; j < 2; j++) {
                wmma::load_matrix_sync(bf[j], &Bs[(ks * 8) * BLD + wc * 32 + j * 16], BLD);
                #pragma unroll
                for (int e = 0; e < bf[j].num_elements; e++) bf[j].x[e] = wmma::__float_to_tf32(bf[j].x[e]);
            }
            #pragma unroll
            for (int i = 0; i < 2; i++)
                #pragma unroll
                for (int j = 0; j < 2; j++)
                    wmma::mma_sync(acc[i][j], af[i], bf[j], acc[i][j]);
        }
        __syncthreads();
    }

    // epilogue: stage each 16x16 tile through smem, fuse bias + relu
    #pragma unroll
    for (int i = 0; i < 2; i++) {
        #pragma unroll
        for (int j = 0; j < 2; j++) {
            wmma::store_matrix_sync(&ebuf[warp][0], acc[i][j], 20, wmma::mem_row_major);
            __syncwarp();
            const int r  = lane >> 1;
            const int cc = (lane & 1) * 8;
            const int gm = m0 + wr * 32 + i * 16 + r;
            const int gn = n0 + wc * 32 + j * 16 + cc;
            float o[8];
            #pragma unroll
            for (int u = 0; u < 8; u++)
                o[u] = fmaxf(ebuf[warp][r * 20 + cc + u] + bias[gn + u], 0.f);
            float4* cp = reinterpret_cast<float4*>(C + (size_t)gm * N + gn);
            cp[0] = make_float4(o[0], o[1], o[2], o[3]);
            cp[1] = make_float4(o[4], o[5], o[6], o[7]);
            __syncwarp();
        }
    }
}

// ---------------------------------------------------------------------------
// Kernel 3: gates (softmax) + expert mix + towers + sigmoid
// ---------------------------------------------------------------------------
__global__ void __launch_bounds__(256)
head_kernel(const float* __restrict__ S, const float* __restrict__ eo,
            const float* __restrict__ gW, const float* __restrict__ gb,
            const float* __restrict__ tW1, const float* __restrict__ tb1,
            const float* __restrict__ tW2, const float* __restrict__ tb2,
            const float* __restrict__ tW3, const float* __restrict__ tb3,
            float* __restrict__ out)
{
    __shared__ float Srow[4][CONCAT];
    __shared__ float gate[4][16];
    __shared__ float ti[4][NTASK][EOUT];
    __shared__ float x1[4][NTASK][64];
    __shared__ float x2[4][NTASK][32];

    const int g = threadIdx.x >> 6;
    const int lane = threadIdx.x & 63;
    const int b = blockIdx.x * 4 + g;

    for (int c = lane; c < CONCAT; c += 64) Srow[g][c] = S[(long)b * CONCAT + c];
    __syncthreads();

    if (lane < 16) {
        const int t = lane >> 3, e = lane & 7;
        float acc = gb[t * 8 + e];
        for (int c = 0; c < CONCAT; c++)
            acc += Srow[g][c] * gW[((long)t * CONCAT + c) * 8 + e];
        gate[g][lane] = acc;
    }
    __syncthreads();
    if (lane < 2) {
        const int t = lane;
        float mx = -3.4e38f;
        for (int e = 0; e < 8; e++) mx = fmaxf(mx, gate[g][t * 8 + e]);
        float sum = 0.f, ex[8];
        for (int e = 0; e < 8; e++) { ex[e] = __expf(gate[g][t * 8 + e] - mx); sum += ex[e]; }
        const float is = 1.f / sum;
        for (int e = 0; e < 8; e++) gate[g][t * 8 + e] = ex[e] * is;
    }
    __syncthreads();

    for (int idx = lane; idx < NTASK * EOUT; idx += 64) {
        const int t = idx >> 7, o = idx & 127;
        float acc = 0.f;
        #pragma unroll
        for (int e = 0; e < 8; e++)
            acc += gate[g][t * 8 + e] * eo[((long)e * BATCH + b) * EOUT + o];
        ti[g][t][o] = acc;
    }
    __syncthreads();

    for (int idx = lane; idx < NTASK * 64; idx += 64) {
        const int t = idx >> 6, j = idx & 63;
        float acc = tb1[t * 64 + j];
        #pragma unroll 4
        for (int o = 0; o < 128; o++)
            acc += ti[g][t][o] * tW1[((long)t * 128 + o) * 64 + j];
        x1[g][t][j] = fmaxf(acc, 0.f);
    }
    __syncthreads();

    {
        const int t = lane >> 5, m = lane & 31;
        float acc = tb2[t * 32 + m];
        #pragma unroll 4
        for (int j = 0; j < 64; j++)
            acc += x1[g][t][j] * tW2[(t * 64 + j) * 32 + m];
        x2[g][t][m] = fmaxf(acc, 0.f);
    }
    __syncthreads();

    if (lane < 2) {
        const int t = lane;
        float acc = tb3[t];
        #pragma unroll
        for (int m = 0; m < 32; m++) acc += x2[g][t][m] * tW3[t * 32 + m];
        out[(long)t * BATCH + b] = 1.f / (1.f + __expf(-acc));
    }
}

// ---------------------------------------------------------------------------
// Launch
// ---------------------------------------------------------------------------
extern "C" void kernel_launch(void* const* d_in, const int* in_sizes, int n_in,
                              void* d_out, int out_size)
{
    const int*   uid    = (const int*)  d_in[0];
    const int*   iid    = (const int*)  d_in[1];
    const int*   cid    = (const int*)  d_in[2];
    const int*   did    = (const int*)  d_in[3];
    const float* udense = (const float*)d_in[4];
    const float* idense = (const float*)d_in[5];
    const int*   hseq   = (const int*)  d_in[6];
    const float* userE  = (const float*)d_in[7];
    const float* itemE  = (const float*)d_in[8];
    const float* catE   = (const float*)d_in[9];
    const float* durE   = (const float*)d_in[10];
    const float* histE  = (const float*)d_in[11];
    const float* Wproj  = (const float*)d_in[12];
    const float* aW1    = (const float*)d_in[13];
    const float* ab1    = (const float*)d_in[14];
    const float* aW2    = (const float*)d_in[15];
    const float* ab2    = (const float*)d_in[16];
    const float* aW3    = (const float*)d_in[17];
    const float* ab3    = (const float*)d_in[18];
    const float* eW1    = (const float*)d_in[19];
    const float* eb1    = (const float*)d_in[20];
    const float* eW2    = (const float*)d_in[21];
    const float* eb2    = (const float*)d_in[22];
    const float* gW     = (const float*)d_in[23];
    const float* gb     = (const float*)d_in[24];
    const float* tW1    = (const float*)d_in[25];
    const float* tb1    = (const float*)d_in[26];
    const float* tW2    = (const float*)d_in[27];
    const float* tb2    = (const float*)d_in[28];
    const float* tW3    = (const float*)d_in[29];
    const float* tb3    = (const float*)d_in[30];
    float* out = (float*)d_out;

    float *pS, *pEh, *pEo;
    cudaGetSymbolAddress((void**)&pS,  g_S);
    cudaGetSymbolAddress((void**)&pEh, g_eh);
    cudaGetSymbolAddress((void**)&pEo, g_eo);

    // K1: attention + feature concat
    attn_kernel<<<BATCH, 256>>>(
        uid, iid, cid, did, udense, idense, hseq,
        userE, itemE, catE, durE, histE, Wproj,
        aW1, ab1, aW2, ab2, aW3, ab3, pS);

    // K2a: eh = relu(S @ eW1 + eb1)  per expert
    wgemm_bias_relu<<<dim3(EHID / GBN, BATCH / GBM, NEXP), 256>>>(
        pS, eW1, eb1, pEh,
        BATCH, EHID, CONCAT,
        (size_t)0, (size_t)CONCAT * EHID, (size_t)EHID, (size_t)BATCH * EHID);

    // K2b: eo = relu(eh @ eW2 + eb2)  per expert
    wgemm_bias_relu<<<dim3(EOUT / GBN, BATCH / GBM, NEXP), 256>>>(
        pEh, eW2, eb2, pEo,
        BATCH, EOUT, EHID,
        (size_t)BATCH * EHID, (size_t)EHID * EOUT, (size_t)EOUT, (size_t)BATCH * EOUT);

    // K3: gates + mix + towers + sigmoid
    head_kernel<<<BATCH / 4, 256>>>(
        pS, pEo, gW, gb, tW1, tb1, tW2, tb2, tW3, tb3, out);
}

// round 4
// speedup vs baseline: 1.4283x; 1.1418x over previous
#include <cuda_runtime.h>
#include <cuda_bf16.h>
#include <mma.h>
#include <math.h>

using namespace nvcuda;

// ---------------------------------------------------------------------------
// Problem constants
// ---------------------------------------------------------------------------
#define BATCH   16384
#define LSEQ    200
#define SDIM    64
#define CONCAT  244
#define NEXP    8
#define EHID    256
#define EOUT    128
#define NTASK   2
#define CHUNK   64     // history positions per chunk (4 x m16 row tiles)
#define HLD     72     // augmented K: 64 data + 1 ones + 7 zero

// ---------------------------------------------------------------------------
// Scratch (static device globals — no allocation allowed)
// ---------------------------------------------------------------------------
__device__ float g_S [(long)BATCH * CONCAT];            // shared feature rows (16 MB)
__device__ float g_eh[(long)NEXP * BATCH * EHID];       // expert hidden (134 MB)
__device__ float g_eo[(long)NEXP * BATCH * EOUT];       // expert out (67 MB)

// ---------------------------------------------------------------------------
// Kernel 1: DIN attention + pooling + feature concat (tf32 WMMA, K-augmented
// bias folding).  One block per batch row, 256 threads (8 warps).
//   layer1 = relu([h | 1] @ [M ; base])   M[k][j] per-row, base row folds ab1
//   layer2 = [h1 | 1] @ [aW2 ; ab2]       (col-64 ones survive in-place store)
// ---------------------------------------------------------------------------
struct AttnSmem {
    float M[HLD * 64];           // rows 0-63: M, row 64: base, 65-71: zero (18.4 KB)
    float hc[CHUNK * HLD];       // history chunk / in-place h1 (18.4 KB)
    union {
        float h2[CHUNK * 16];    // layer2 pre-activations (4 KB)
        struct {
            float pool[4][64];
            float poolred[64];
            float red[32];
        } t;
    } u;
    float aW2s[HLD * 16];        // rows 0-63: aW2, row 64: ab2, 65-71: 0 (4.6 KB)
    float tvec[64];
    float ibuf[64];
    float aW3s[16];
    int   seqs[LSEQ];
    float scores[LSEQ];          // reused in place as attn weights
};

__global__ void __launch_bounds__(256)
attn_kernel(const int* __restrict__ uid, const int* __restrict__ iid,
            const int* __restrict__ cid, const int* __restrict__ did,
            const float* __restrict__ udense, const float* __restrict__ idense,
            const int* __restrict__ hseq,
            const float* __restrict__ userE, const float* __restrict__ itemE,
            const float* __restrict__ catE,  const float* __restrict__ durE,
            const float* __restrict__ histE, const float* __restrict__ Wproj,
            const float* __restrict__ aW1, const float* __restrict__ ab1,
            const float* __restrict__ aW2, const float* __restrict__ ab2,
            const float* __restrict__ aW3, const float* __restrict__ ab3,
            float* __restrict__ Sout)
{
    __shared__ AttnSmem s;

    const int b    = blockIdx.x;
    const int tid  = threadIdx.x;
    const int lane = tid & 31;
    const int warp = tid >> 5;

    // ---- stage constants + item embedding + sequence ids ----
    const int item = iid[b];
    if (tid < 64) s.ibuf[tid] = itemE[(long)item * 64 + tid];
    for (int i = tid; i < HLD * 16; i += 256) {
        const int r = i >> 4, c = i & 15;
        s.aW2s[i] = (r < 64) ? aW2[i] : ((r == 64) ? ab2[c] : 0.f);
    }
    if (tid < 16) s.aW3s[tid] = aW3[tid];
    for (int l = tid; l < LSEQ; l += 256) s.seqs[l] = hseq[(long)b * LSEQ + l];
    // augmented columns of hc: col 64 = 1.0, cols 65-71 = 0 (never overwritten:
    // gather + layer1 stores touch cols 0-63 only)
    if (tid < 64) {
        s.hc[tid * HLD + 64] = 1.f;
        #pragma unroll
        for (int q = 65; q < HLD; q++) s.hc[tid * HLD + q] = 0.f;
    }
    __syncthreads();

    // ---- t = i_emb @ Wproj ----
    if (tid < 64) {
        float acc = 0.f;
        #pragma unroll 4
        for (int k = 0; k < 64; k++) acc += s.ibuf[k] * Wproj[k * 64 + tid];
        s.tvec[tid] = acc;
    }
    __syncthreads();

    // ---- M rows 0..63 and base row 64 (incl ab1), rows 65..71 zero ----
    if (tid < 64) {
        float acc = ab1[tid];
        #pragma unroll 4
        for (int k = 0; k < 64; k++)
            acc += s.tvec[k] * (aW1[k * 64 + tid] + aW1[(128 + k) * 64 + tid]);
        s.M[64 * 64 + tid] = acc;
    }
    for (int idx = tid; idx < 64 * 64; idx += 256) {
        const int k = idx >> 6, j = idx & 63;
        s.M[idx] = aW1[(64 + k) * 64 + j] - aW1[(128 + k) * 64 + j]
                 + s.tvec[k] * aW1[(192 + k) * 64 + j];
    }
    for (int i = 65 * 64 + tid; i < HLD * 64; i += 256) s.M[i] = 0.f;
    __syncthreads();

    const float ab3v = ab3[0];

    // ---- chunk loop: 4 chunks of 64 positions ----
    for (int c0 = 0; c0 < LSEQ; c0 += CHUNK) {
        // gather 64x64 chunk (float4, histE L2-resident)
        #pragma unroll
        for (int h = 0; h < 4; h++) {
            const int idx = tid + h * 256;          // 0..1023
            const int row = idx >> 4;               // 0..63
            const int c4  = (idx & 15) * 4;         // 0..60
            const int l = c0 + row;
            float4 v = make_float4(0.f, 0.f, 0.f, 0.f);
            if (l < LSEQ)
                v = *reinterpret_cast<const float4*>(histE + (long)s.seqs[l] * 64 + c4);
            *reinterpret_cast<float4*>(&s.hc[row * HLD + c4]) = v;
        }
        __syncthreads();

        // layer 1: h1(64x64) = relu([h|1](64x72) @ [M;base](72x64)), in place
        {
            const int r  = warp & 3;                // row tile 0..3
            const int cp = warp >> 2;               // col pair 0..1
            wmma::fragment<wmma::accumulator, 16, 16, 8, float> acc0, acc1;
            wmma::fill_fragment(acc0, 0.f);
            wmma::fill_fragment(acc1, 0.f);
            #pragma unroll
            for (int ks = 0; ks < HLD / 8; ks++) {
                wmma::fragment<wmma::matrix_a, 16, 16, 8, wmma::precision::tf32, wmma::row_major> af;
                wmma::fragment<wmma::matrix_b, 16, 16, 8, wmma::precision::tf32, wmma::row_major> b0, b1;
                wmma::load_matrix_sync(af, &s.hc[(r * 16) * HLD + ks * 8], HLD);
                wmma::load_matrix_sync(b0, &s.M[(ks * 8) * 64 + cp * 32], 64);
                wmma::load_matrix_sync(b1, &s.M[(ks * 8) * 64 + cp * 32 + 16], 64);
                #pragma unroll
                for (int i = 0; i < af.num_elements; i++) af.x[i] = wmma::__float_to_tf32(af.x[i]);
                #pragma unroll
                for (int i = 0; i < b0.num_elements; i++) b0.x[i] = wmma::__float_to_tf32(b0.x[i]);
                #pragma unroll
                for (int i = 0; i < b1.num_elements; i++) b1.x[i] = wmma::__float_to_tf32(b1.x[i]);
                wmma::mma_sync(acc0, af, b0, acc0);
                wmma::mma_sync(acc1, af, b1, acc1);
            }
            #pragma unroll
            for (int i = 0; i < acc0.num_elements; i++) acc0.x[i] = fmaxf(acc0.x[i], 0.f);
            #pragma unroll
            for (int i = 0; i < acc1.num_elements; i++) acc1.x[i] = fmaxf(acc1.x[i], 0.f);
            __syncthreads();   // all hc reads complete before in-place overwrite
            wmma::store_matrix_sync(&s.hc[(r * 16) * HLD + cp * 32],      acc0, HLD, wmma::mem_row_major);
            wmma::store_matrix_sync(&s.hc[(r * 16) * HLD + cp * 32 + 16], acc1, HLD, wmma::mem_row_major);
        }
        __syncthreads();

        // layer 2: h2(64x16) = [h1|1](64x72) @ [aW2;ab2](72x16), warps 0-3
        if (warp < 4) {
            wmma::fragment<wmma::accumulator, 16, 16, 8, float> accf;
            wmma::fill_fragment(accf, 0.f);
            #pragma unroll
            for (int ks = 0; ks < HLD / 8; ks++) {
                wmma::fragment<wmma::matrix_a, 16, 16, 8, wmma::precision::tf32, wmma::row_major> af;
                wmma::fragment<wmma::matrix_b, 16, 16, 8, wmma::precision::tf32, wmma::row_major> bf;
                wmma::load_matrix_sync(af, &s.hc[(warp * 16) * HLD + ks * 8], HLD);
                wmma::load_matrix_sync(bf, &s.aW2s[(ks * 8) * 16], 16);
                #pragma unroll
                for (int i = 0; i < af.num_elements; i++) af.x[i] = wmma::__float_to_tf32(af.x[i]);
                #pragma unroll
                for (int i = 0; i < bf.num_elements; i++) bf.x[i] = wmma::__float_to_tf32(bf.x[i]);
                wmma::mma_sync(accf, af, bf, accf);
            }
            wmma::store_matrix_sync(&s.u.h2[(warp * 16) * 16], accf, 16, wmma::mem_row_major);
        }
        __syncthreads();

        // layer 3 + mask: 64 lanes, one position each
        if (tid < 64) {
            float val = 0.f;
            #pragma unroll
            for (int m = 0; m < 16; m++)
                val += fmaxf(s.u.h2[tid * 16 + m], 0.f) * s.aW3s[m];
            const int l = c0 + tid;
            if (l < LSEQ)
                s.scores[l] = (s.seqs[l] == 0) ? -1e9f : (val + ab3v);
        }
        // no trailing sync needed: next gather only writes hc (readers done),
        // and the gather's own __syncthreads orders scores consumers later
    }
    __syncthreads();

    // ---- softmax over L (in place in scores) ----
    float sv = (tid < LSEQ) ? s.scores[tid] : -3.4e38f;
    {
        float m = sv;
        #pragma unroll
        for (int off = 16; off >= 1; off >>= 1)
            m = fmaxf(m, __shfl_xor_sync(0xffffffffu, m, off));
        if (lane == 0) s.u.t.red[warp] = m;
    }
    __syncthreads();
    if (tid == 0) {
        float mm = s.u.t.red[0];
        for (int w = 1; w < 8; w++) mm = fmaxf(mm, s.u.t.red[w]);
        s.u.t.red[16] = mm;
    }
    __syncthreads();
    const float smax = s.u.t.red[16];
    float e = (tid < LSEQ) ? __expf(sv - smax) : 0.f;
    {
        float sum = e;
        #pragma unroll
        for (int off = 16; off >= 1; off >>= 1)
            sum += __shfl_xor_sync(0xffffffffu, sum, off);
        if (lane == 0) s.u.t.red[warp + 8] = sum;
    }
    __syncthreads();
    if (tid == 0) {
        float ss = 0.f;
        for (int w = 0; w < 8; w++) ss += s.u.t.red[w + 8];
        s.u.t.red[17] = 1.f / ss;
    }
    __syncthreads();
    const float inv = s.u.t.red[17];
    if (tid < LSEQ) s.scores[tid] = e * inv;
    __syncthreads();

    // ---- pooled = attn @ h (re-gather, L2-resident) ----
    {
        const int d = tid & 63, g = tid >> 6;
        float acc = 0.f;
        for (int l = g; l < LSEQ; l += 4)
            acc += s.scores[l] * histE[(long)s.seqs[l] * 64 + d];
        s.u.t.pool[g][d] = acc;
    }
    __syncthreads();
    if (tid < 64)
        s.u.t.poolred[tid] = s.u.t.pool[0][tid] + s.u.t.pool[1][tid]
                           + s.u.t.pool[2][tid] + s.u.t.pool[3][tid];
    __syncthreads();

    // ---- write feature row ----
    if (tid < CONCAT) {
        float v;
        if      (tid < 64)  v = userE[(long)uid[b] * 64 + tid];
        else if (tid < 128) v = s.ibuf[tid - 64];
        else if (tid < 144) v = catE[(long)cid[b] * 16 + (tid - 128)];
        else if (tid < 152) v = durE[(long)did[b] * 8 + (tid - 144)];
        else if (tid < 177) v = udense[(long)b * 25 + (tid - 152)];
        else if (tid < 180) v = idense[(long)b * 3 + (tid - 177)];
        else                v = s.u.t.poolred[tid - 180];
        Sout[(long)b * CONCAT + tid] = v;
    }
}

// ---------------------------------------------------------------------------
// Kernel 2: batched tf32 WMMA GEMM + bias + ReLU, 2-stage cp.async pipeline
// C[z] = relu(A[z] (MxK) @ B[z] (KxN) + bias[z])
// Block tile 128x128, BK=16, 256 threads, warp tile 64x32 (2x4 warp grid).
// ---------------------------------------------------------------------------
#define TBM 128
#define TBN 128
#define TBK 16
#define ALD 24       // TBK + 8
#define BLD 136      // TBN + 8

__device__ __forceinline__ void cp_async16(void* smem_dst, const void* gsrc) {
    unsigned sm = (unsigned)__cvta_generic_to_shared(smem_dst);
    asm volatile("cp.async.cg.shared.global [%0], [%1], 16;\n" :: "r"(sm), "l"(gsrc));
}
__device__ __forceinline__ void cp_commit() {
    asm volatile("cp.async.commit_group;\n");
}
template <int N>
__device__ __forceinline__ void cp_wait() {
    asm volatile("cp.async.wait_group %0;\n" :: "n"(N));
}

struct GemmSmem {
    union {
        struct {
            float As[2][TBM * ALD];
            float Bs[2][TBK * BLD];
        } p;
        float ebuf[8][16 * 20];
    } u;
};

__global__ void __launch_bounds__(256, 2)
wgemm_bias_relu(const float* __restrict__ A, const float* __restrict__ Bw,
                const float* __restrict__ bias, float* __restrict__ C,
                int M, int N, int K,
                size_t sA, size_t sB, size_t sBias, size_t sC)
{
    __shared__ GemmSmem sm;

    const int z = blockIdx.z;
    A += (size_t)z * sA; Bw += (size_t)z * sB;
    bias += (size_t)z * sBias; C += (size_t)z * sC;

    const int m0 = blockIdx.y * TBM;
    const int n0 = blockIdx.x * TBN;
    const int tid = threadIdx.x;
    const int lane = tid & 31;
    const int warp = tid >> 5;
    const int wr = warp >> 2;            // 0..1
    const int wc = warp & 3;             // 0..3

    // per-thread load coords
    const int a_row = tid >> 2;          // 0..63 (x2 halves)
    const int a_c4  = (tid & 3) * 4;     // 0,4,8,12
    const int b_row = tid >> 5;          // 0..7 (x2 halves)
    const int b_c4  = (tid & 31) * 4;    // 0..124

    const int nk = (K + TBK - 1) / TBK;

    auto load_stage = [&](int st, int k0) {
        // A tile: 128 x 16
        #pragma unroll
        for (int h = 0; h < 2; h++) {
            const int row = a_row + h * 64;
            float* dst = &sm.u.p.As[st][row * ALD + a_c4];
            const int k = k0 + a_c4;
            if (k + 3 < K)
                cp_async16(dst, A + (size_t)(m0 + row) * K + k);
            else if (k < K) {           // partial (K%4==0 cases only hit exact)
                cp_async16(dst, A + (size_t)(m0 + row) * K + k);
            } else {
                dst[0] = 0.f; dst[1] = 0.f; dst[2] = 0.f; dst[3] = 0.f;
            }
        }
        // B tile: 16 x 128
        #pragma unroll
        for (int h = 0; h < 2; h++) {
            const int row = b_row + h * 8;
            float* dst = &sm.u.p.Bs[st][row * BLD + b_c4];
            const int k = k0 + row;
            if (k < K)
                cp_async16(dst, Bw + (size_t)k * N + n0 + b_c4);
            else {
                dst[0] = 0.f; dst[1] = 0.f; dst[2] = 0.f; dst[3] = 0.f;
            }
        }
    };

    wmma::fragment<wmma::accumulator, 16, 16, 8, float> acc[4][2];
    #pragma unroll
    for (int i = 0; i < 4; i++)
        #pragma unroll
        for (int j = 0; j < 2; j++) wmma::fill_fragment(acc[i][j], 0.f);

    load_stage(0, 0);
    cp_commit();

    for (int kt = 0; kt < nk; kt++) {
        if (kt + 1 < nk) {
            load_stage((kt + 1) & 1, (kt + 1) * TBK);
            cp_commit();
            cp_wait<1>();
        } else {
            cp_wait<0>();
        }
        __syncthreads();

        const int st = kt & 1;
        #pragma unroll
        for (int ks = 0; ks < TBK / 8; ks++) {
            wmma::fragment<wmma::matrix_a, 16, 16, 8, wmma::precision::tf32, wmma::row_major> af[4];
            wmma::fragment<wmma::matrix_b, 16, 16, 8, wmma::precision::tf32, wmma::row_major> bf[2];
            #pragma unroll
            for (int i = 0; i < 4; i++) {
                wmma::load_matrix_sync(af[i], &sm.u.p.As[st][(wr * 64 + i * 16) * ALD + ks * 8], ALD);
                #pragma unroll
                for (int e = 0; e < af[i].num_elements; e++) af[i].x[e] = wmma::__float_to_tf32(af[i].x[e]);
            }
            #pragma unroll
            for (int j = 0; j < 2; j++) {
                wmma::load_matrix_sync(bf[j], &sm.u.p.Bs[st][(ks * 8) * BLD + wc * 32 + j * 16], BLD);
                #pragma unroll
                for (int e = 0; e < bf[j].num_elements; e++) bf[j].x[e] = wmma::__float_to_tf32(bf[j].x[e]);
            }
            #pragma unroll
            for (int i = 0; i < 4; i++)
                #pragma unroll
                for (int j = 0; j < 2; j++)
                    wmma::mma_sync(acc[i][j], af[i], bf[j], acc[i][j]);
        }
        __syncthreads();
    }

    // epilogue: stage tiles through smem (unioned with pipeline buffers)
    #pragma unroll
    for (int i = 0; i < 4; i++) {
        #pragma unroll
        for (int j = 0; j < 2; j++) {
            wmma::store_matrix_sync(&sm.u.ebuf[warp][0], acc[i][j], 20, wmma::mem_row_major);
            __syncwarp();
            const int r  = lane >> 1;
            const int cc = (lane & 1) * 8;
            const int gm = m0 + wr * 64 + i * 16 + r;
            const int gn = n0 + wc * 32 + j * 16 + cc;
            float o[8];
            #pragma unroll
            for (int u = 0; u < 8; u++)
                o[u] = fmaxf(sm.u.ebuf[warp][r * 20 + cc + u] + bias[gn + u], 0.f);
            float4* cp = reinterpret_cast<float4*>(C + (size_t)gm * N + gn);
            cp[0] = make_float4(o[0], o[1], o[2], o[3]);
            cp[1] = make_float4(o[4], o[5], o[6], o[7]);
            __syncwarp();
        }
    }
}

// ---------------------------------------------------------------------------
// Kernel 3: gates (softmax) + expert mix + towers + sigmoid
// 256 threads = 4 groups of 64 lanes; one batch row per group.
// ---------------------------------------------------------------------------
__global__ void __launch_bounds__(256)
head_kernel(const float* __restrict__ S, const float* __restrict__ eo,
            const float* __restrict__ gW, const float* __restrict__ gb,
            const float* __restrict__ tW1, const float* __restrict__ tb1,
            const float* __restrict__ tW2, const float* __restrict__ tb2,
            const float* __restrict__ tW3, const float* __restrict__ tb3,
            float* __restrict__ out)
{
    __shared__ float Srow[4][CONCAT];
    __shared__ float gate[4][16];
    __shared__ float ti[4][NTASK][EOUT];
    __shared__ float x1[4][NTASK][64];
    __shared__ float x2[4][NTASK][32];

    const int g = threadIdx.x >> 6;
    const int lane = threadIdx.x & 63;
    const int b = blockIdx.x * 4 + g;

    for (int c = lane; c < CONCAT; c += 64) Srow[g][c] = S[(long)b * CONCAT + c];
    __syncthreads();

    // gate logits: all 64 lanes, 4-way K-split + shfl reduce
    {
        const int o = lane >> 2;                 // 0..15
        const int q = lane & 3;
        const int t = o >> 3, e = o & 7;
        const int c0 = q * 61;                   // 4*61 = 244
        float acc = 0.f;
        #pragma unroll 8
        for (int c = c0; c < c0 + 61; c++)
            acc += Srow[g][c] * __ldg(&gW[((long)t * CONCAT + c) * 8 + e]);
        acc += __shfl_xor_sync(0xffffffffu, acc, 1);
        acc += __shfl_xor_sync(0xffffffffu, acc, 2);
        if (q == 0) gate[g][o] = acc + gb[t * 8 + e];
    }
    __syncthreads();
    // softmax over experts
    if (lane < 2) {
        const int t = lane;
        float mx = -3.4e38f;
        for (int e = 0; e < 8; e++) mx = fmaxf(mx, gate[g][t * 8 + e]);
        float sum = 0.f, ex[8];
        for (int e = 0; e < 8; e++) { ex[e] = __expf(gate[g][t * 8 + e] - mx); sum += ex[e]; }
        const float is = 1.f / sum;
        for (int e = 0; e < 8; e++) gate[g][t * 8 + e] = ex[e] * is;
    }
    __syncthreads();

    // mix experts (float4): ti[t][o] = sum_e gate[t][e] * eo[e][b][o]
    {
        const int t = lane >> 5;
        const int o = (lane & 31) * 4;
        float4 acc = make_float4(0.f, 0.f, 0.f, 0.f);
        #pragma unroll
        for (int e = 0; e < 8; e++) {
            const float gv = gate[g][t * 8 + e];
            const float4 v = *reinterpret_cast<const float4*>(
                eo + ((long)e * BATCH + b) * EOUT + o);
            acc.x += gv * v.x; acc.y += gv * v.y;
            acc.z += gv * v.z; acc.w += gv * v.w;
        }
        *reinterpret_cast<float4*>(&ti[g][t][o]) = acc;
    }
    __syncthreads();

    // tower layer 1: 128 -> 64 (2 tasks over 2 passes)
    for (int idx = lane; idx < NTASK * 64; idx += 64) {
        const int t = idx >> 6, j = idx & 63;
        float acc = tb1[t * 64 + j];
        #pragma unroll 8
        for (int o = 0; o < 128; o++)
            acc += ti[g][t][o] * __ldg(&tW1[((long)t * 128 + o) * 64 + j]);
        x1[g][t][j] = fmaxf(acc, 0.f);
    }
    __syncthreads();

    // tower layer 2: 64 -> 32
    {
        const int t = lane >> 5, m = lane & 31;
        float acc = tb2[t * 32 + m];
        #pragma unroll 8
        for (int j = 0; j < 64; j++)
            acc += x1[g][t][j] * __ldg(&tW2[(t * 64 + j) * 32 + m]);
        x2[g][t][m] = fmaxf(acc, 0.f);
    }
    __syncthreads();

    // tower layer 3 + sigmoid
    if (lane < 2) {
        const int t = lane;
        float acc = tb3[t];
        #pragma unroll
        for (int m = 0; m < 32; m++) acc += x2[g][t][m] * tW3[t * 32 + m];
        out[(long)t * BATCH + b] = 1.f / (1.f + __expf(-acc));
    }
}

// ---------------------------------------------------------------------------
// Launch
// ---------------------------------------------------------------------------
extern "C" void kernel_launch(void* const* d_in, const int* in_sizes, int n_in,
                              void* d_out, int out_size)
{
    const int*   uid    = (const int*)  d_in[0];
    const int*   iid    = (const int*)  d_in[1];
    const int*   cid    = (const int*)  d_in[2];
    const int*   did    = (const int*)  d_in[3];
    const float* udense = (const float*)d_in[4];
    const float* idense = (const float*)d_in[5];
    const int*   hseq   = (const int*)  d_in[6];
    const float* userE  = (const float*)d_in[7];
    const float* itemE  = (const float*)d_in[8];
    const float* catE   = (const float*)d_in[9];
    const float* durE   = (const float*)d_in[10];
    const float* histE  = (const float*)d_in[11];
    const float* Wproj  = (const float*)d_in[12];
    const float* aW1    = (const float*)d_in[13];
    const float* ab1    = (const float*)d_in[14];
    const float* aW2    = (const float*)d_in[15];
    const float* ab2    = (const float*)d_in[16];
    const float* aW3    = (const float*)d_in[17];
    const float* ab3    = (const float*)d_in[18];
    const float* eW1    = (const float*)d_in[19];
    const float* eb1    = (const float*)d_in[20];
    const float* eW2    = (const float*)d_in[21];
    const float* eb2    = (const float*)d_in[22];
    const float* gW     = (const float*)d_in[23];
    const float* gb     = (const float*)d_in[24];
    const float* tW1    = (const float*)d_in[25];
    const float* tb1    = (const float*)d_in[26];
    const float* tW2    = (const float*)d_in[27];
    const float* tb2    = (const float*)d_in[28];
    const float* tW3    = (const float*)d_in[29];
    const float* tb3    = (const float*)d_in[30];
    float* out = (float*)d_out;

    float *pS, *pEh, *pEo;
    cudaGetSymbolAddress((void**)&pS,  g_S);
    cudaGetSymbolAddress((void**)&pEh, g_eh);
    cudaGetSymbolAddress((void**)&pEo, g_eo);

    // K1: attention + feature concat
    attn_kernel<<<BATCH, 256>>>(
        uid, iid, cid, did, udense, idense, hseq,
        userE, itemE, catE, durE, histE, Wproj,
        aW1, ab1, aW2, ab2, aW3, ab3, pS);

    // K2a: eh = relu(S @ eW1 + eb1)  per expert
    wgemm_bias_relu<<<dim3(EHID / TBN, BATCH / TBM, NEXP), 256>>>(
        pS, eW1, eb1, pEh,
        BATCH, EHID, CONCAT,
        (size_t)0, (size_t)CONCAT * EHID, (size_t)EHID, (size_t)BATCH * EHID);

    // K2b: eo = relu(eh @ eW2 + eb2)  per expert
    wgemm_bias_relu<<<dim3(EOUT / TBN, BATCH / TBM, NEXP), 256>>>(
        pEh, eW2, eb2, pEo,
        BATCH, EOUT, EHID,
        (size_t)BATCH * EHID, (size_t)EHID * EOUT, (size_t)EOUT, (size_t)BATCH * EOUT);

    // K3: gates + mix + towers + sigmoid
    head_kernel<<<BATCH / 4, 256>>>(
        pS, pEo, gW, gb, tW1, tb1, tW2, tb2, tW3, tb3, out);
}

// round 5
// speedup vs baseline: 1.6143x; 1.1302x over previous
#include <cuda_runtime.h>
#include <cuda_bf16.h>
#include <mma.h>
#include <math.h>

using namespace nvcuda;

// ---------------------------------------------------------------------------
// Problem constants
// ---------------------------------------------------------------------------
#define BATCH   16384
#define LSEQ    200
#define CONCAT  244
#define NEXP    8
#define EHID    256
#define EOUT    128
#define NTASK   2
#define CHUNK   64
#define HLD     72     // 64 data + 1 ones + 7 zero (augmented K)

// ---------------------------------------------------------------------------
// Scratch (static device globals — no allocation allowed)
// ---------------------------------------------------------------------------
__device__ float g_S [(long)BATCH * CONCAT];
__device__ float g_eh[(long)NEXP * BATCH * EHID];
__device__ float g_eo[(long)NEXP * BATCH * EOUT];

// ---------------------------------------------------------------------------
// cp.async helpers
// ---------------------------------------------------------------------------
__device__ __forceinline__ void cp_async16(void* smem_dst, const void* gsrc) {
    unsigned sm = (unsigned)__cvta_generic_to_shared(smem_dst);
    asm volatile("cp.async.cg.shared.global [%0], [%1], 16;\n" :: "r"(sm), "l"(gsrc));
}
__device__ __forceinline__ void cp_async16z(void* smem_dst, const void* gsrc, int srcbytes) {
    unsigned sm = (unsigned)__cvta_generic_to_shared(smem_dst);
    asm volatile("cp.async.cg.shared.global [%0], [%1], 16, %2;\n"
                 :: "r"(sm), "l"(gsrc), "r"(srcbytes));
}
__device__ __forceinline__ void cp_commit() {
    asm volatile("cp.async.commit_group;\n");
}
template <int N>
__device__ __forceinline__ void cp_wait() {
    asm volatile("cp.async.wait_group %0;\n" :: "n"(N));
}

// raw tf32 mma: D += A(16x8,row) * B(8x8,col); operands are fp32 bit patterns
__device__ __forceinline__ void mma_tf32(float* d, const float* a, const float* b) {
    asm volatile(
        "mma.sync.aligned.m16n8k8.row.col.f32.tf32.tf32.f32 "
        "{%0,%1,%2,%3}, {%4,%5,%6,%7}, {%8,%9}, {%0,%1,%2,%3};\n"
        : "+f"(d[0]), "+f"(d[1]), "+f"(d[2]), "+f"(d[3])
        : "r"(__float_as_uint(a[0])), "r"(__float_as_uint(a[1])),
          "r"(__float_as_uint(a[2])), "r"(__float_as_uint(a[3])),
          "r"(__float_as_uint(b[0])), "r"(__float_as_uint(b[1])));
}

// ---------------------------------------------------------------------------
// Kernel 1: DIN attention + fused online pooling + feature concat
// One block per batch row, 256 threads (8 warps), dynamic smem (~84 KB).
// ---------------------------------------------------------------------------
struct AttnSmem {
    float gb[2][CHUNK * HLD];    // gather double buffer (incl ones col 64)
    float h1[CHUNK * HLD];       // layer1 out (incl ones col 64)
    float M[HLD * 64];           // rows 0-63: M, row 64: base(+ab1), 65-71: 0
    float aW2s[HLD * 16];        // rows 0-63: aW2, row 64: ab2, 65-71: 0
    float h2[CHUNK * 16];
    float part[4][64];           // matvec partials / pooling partials
    float ibuf[64];
    float tvec[64];
    float sc[CHUNK];             // chunk exp-weights
    float poolred[64];
    float aW3s[16];
    float red[16];               // [0],[1]: warp sums; [2]: running denom
    int   seqs[LSEQ];
};

__global__ void __launch_bounds__(256)
attn_kernel(const int* __restrict__ uid, const int* __restrict__ iid,
            const int* __restrict__ cid, const int* __restrict__ did,
            const float* __restrict__ udense, const float* __restrict__ idense,
            const int* __restrict__ hseq,
            const float* __restrict__ userE, const float* __restrict__ itemE,
            const float* __restrict__ catE,  const float* __restrict__ durE,
            const float* __restrict__ histE, const float* __restrict__ Wproj,
            const float* __restrict__ aW1, const float* __restrict__ ab1,
            const float* __restrict__ aW2, const float* __restrict__ ab2,
            const float* __restrict__ aW3, const float* __restrict__ ab3,
            float* __restrict__ Sout)
{
    extern __shared__ unsigned char smem_raw[];
    AttnSmem& s = *reinterpret_cast<AttnSmem*>(smem_raw);

    const int b    = blockIdx.x;
    const int tid  = threadIdx.x;
    const int lane = tid & 31;
    const int warp = tid >> 5;

    // ---- stage constants + sequence ids; init ones cols + running state ----
    const int item = iid[b];
    if (tid < 64) s.ibuf[tid] = itemE[(long)item * 64 + tid];
    for (int i = tid; i < HLD * 16; i += 256) {
        const int r = i >> 4, c = i & 15;
        s.aW2s[i] = (r < 64) ? aW2[i] : ((r == 64) ? ab2[c] : 0.f);
    }
    if (tid < 16) s.aW3s[tid] = aW3[tid];
    for (int l = tid; l < LSEQ; l += 256) s.seqs[l] = hseq[(long)b * LSEQ + l];
    if (tid < 64) {
        s.gb[0][tid * HLD + 64] = 1.f;
        s.gb[1][tid * HLD + 64] = 1.f;
        s.h1[tid * HLD + 64]    = 1.f;
        #pragma unroll
        for (int q = 65; q < HLD; q++) {
            s.gb[0][tid * HLD + q] = 0.f;
            s.gb[1][tid * HLD + q] = 0.f;
            s.h1[tid * HLD + q]    = 0.f;
        }
    }
    if (tid == 0) s.red[2] = 0.f;
    __syncthreads();

    // ---- issue gather of chunk 0 (overlaps with setup math below) ----
    {
        #pragma unroll
        for (int h = 0; h < 4; h++) {
            const int idx = tid + h * 256;
            const int row = idx >> 4;
            const int c4  = (idx & 15) * 4;
            const int sid = s.seqs[row];            // rows 0..63 < LSEQ
            cp_async16(&s.gb[0][row * HLD + c4], histE + (long)sid * 64 + c4);
        }
        cp_commit();
    }

    // ---- tvec = i_emb @ Wproj (256-thread, 4-way K split) ----
    {
        const int j = tid & 63, q = tid >> 6;
        float acc = 0.f;
        #pragma unroll
        for (int k = q * 16; k < q * 16 + 16; k++)
            acc += s.ibuf[k] * Wproj[k * 64 + j];
        s.part[q][j] = acc;
    }
    __syncthreads();
    if (tid < 64)
        s.tvec[tid] = s.part[0][tid] + s.part[1][tid] + s.part[2][tid] + s.part[3][tid];
    __syncthreads();

    // ---- base row (M row 64) + M rows 0..63 + zero rows 65..71 ----
    if (tid < 64) {
        float acc = ab1[tid];
        #pragma unroll 4
        for (int k = 0; k < 64; k++)
            acc += s.tvec[k] * (aW1[k * 64 + tid] + aW1[(128 + k) * 64 + tid]);
        s.M[64 * 64 + tid] = acc;
    }
    for (int idx = tid; idx < 64 * 64; idx += 256) {
        const int k = idx >> 6, j = idx & 63;
        s.M[idx] = aW1[(64 + k) * 64 + j] - aW1[(128 + k) * 64 + j]
                 + s.tvec[k] * aW1[(192 + k) * 64 + j];
    }
    for (int i = 65 * 64 + tid; i < HLD * 64; i += 256) s.M[i] = 0.f;
    // re-zero partials for pooling accumulation
    s.part[tid >> 6][tid & 63] = 0.f;
    __syncthreads();

    const float ab3v = ab3[0];

    // ---- chunk loop (4 chunks of 64 positions, pipelined gathers) ----
    for (int c = 0; c < 4; c++) {
        const int buf = c & 1;
        if (c < 3) {
            const int c0n = (c + 1) * CHUNK;
            #pragma unroll
            for (int h = 0; h < 4; h++) {
                const int idx = tid + h * 256;
                const int row = idx >> 4;
                const int c4  = (idx & 15) * 4;
                const int l = c0n + row;
                const int sid = (l < LSEQ) ? s.seqs[l] : 0;   // row 0 is zeros
                cp_async16(&s.gb[buf ^ 1][row * HLD + c4], histE + (long)sid * 64 + c4);
            }
            cp_commit();
            cp_wait<1>();
        } else {
            cp_wait<0>();
        }
        __syncthreads();

        // layer 1: h1(64x64) = relu([h|1] @ [M;base]) -> s.h1 (cols 0..63)
        {
            const int r  = warp & 3;
            const int cp = warp >> 2;
            wmma::fragment<wmma::accumulator, 16, 16, 8, float> acc0, acc1;
            wmma::fill_fragment(acc0, 0.f);
            wmma::fill_fragment(acc1, 0.f);
            #pragma unroll
            for (int ks = 0; ks < HLD / 8; ks++) {
                wmma::fragment<wmma::matrix_a, 16, 16, 8, wmma::precision::tf32, wmma::row_major> af;
                wmma::fragment<wmma::matrix_b, 16, 16, 8, wmma::precision::tf32, wmma::row_major> b0, b1;
                wmma::load_matrix_sync(af, &s.gb[buf][(r * 16) * HLD + ks * 8], HLD);
                wmma::load_matrix_sync(b0, &s.M[(ks * 8) * 64 + cp * 32], 64);
                wmma::load_matrix_sync(b1, &s.M[(ks * 8) * 64 + cp * 32 + 16], 64);
                wmma::mma_sync(acc0, af, b0, acc0);
                wmma::mma_sync(acc1, af, b1, acc1);
            }
            #pragma unroll
            for (int i = 0; i < acc0.num_elements; i++) acc0.x[i] = fmaxf(acc0.x[i], 0.f);
            #pragma unroll
            for (int i = 0; i < acc1.num_elements; i++) acc1.x[i] = fmaxf(acc1.x[i], 0.f);
            wmma::store_matrix_sync(&s.h1[(r * 16) * HLD + cp * 32],      acc0, HLD, wmma::mem_row_major);
            wmma::store_matrix_sync(&s.h1[(r * 16) * HLD + cp * 32 + 16], acc1, HLD, wmma::mem_row_major);
        }
        __syncthreads();

        // layer 2: h2(64x16) = [h1|1] @ [aW2;ab2]  (warps 0-3)
        if (warp < 4) {
            wmma::fragment<wmma::accumulator, 16, 16, 8, float> accf;
            wmma::fill_fragment(accf, 0.f);
            #pragma unroll
            for (int ks = 0; ks < HLD / 8; ks++) {
                wmma::fragment<wmma::matrix_a, 16, 16, 8, wmma::precision::tf32, wmma::row_major> af;
                wmma::fragment<wmma::matrix_b, 16, 16, 8, wmma::precision::tf32, wmma::row_major> bf;
                wmma::load_matrix_sync(af, &s.h1[(warp * 16) * HLD + ks * 8], HLD);
                wmma::load_matrix_sync(bf, &s.aW2s[(ks * 8) * 16], 16);
                wmma::mma_sync(accf, af, bf, accf);
            }
            wmma::store_matrix_sync(&s.h2[(warp * 16) * 16], accf, 16, wmma::mem_row_major);
        }
        __syncthreads();

        // layer 3: un-normalized softmax weights w = exp(score) (scores ~ O(1))
        if (tid < 64) {
            float val = 0.f;
            #pragma unroll
            for (int m = 0; m < 16; m++)
                val += fmaxf(s.h2[tid * 16 + m], 0.f) * s.aW3s[m];
            const int l = c * CHUNK + tid;
            float w = 0.f;
            if (l < LSEQ && s.seqs[l] != 0) w = __expf(val + ab3v);
            s.sc[tid] = w;
            // warp-level sum (warps 0 and 1)
            float sum = w;
            #pragma unroll
            for (int off = 16; off >= 1; off >>= 1)
                sum += __shfl_xor_sync(0xffffffffu, sum, off);
            if (lane == 0) s.red[warp] = sum;
        }
        __syncthreads();
        if (tid == 0) s.red[2] += s.red[0] + s.red[1];

        // pooling accumulation: part[g][d] += sum_l w_l * h[l][d]
        {
            const int d = tid & 63, g = tid >> 6;
            float acc = s.part[g][d];
            #pragma unroll
            for (int i = 0; i < 16; i++) {
                const int l = g * 16 + i;
                acc += s.sc[l] * s.gb[buf][l * HLD + d];
            }
            s.part[g][d] = acc;
        }
        __syncthreads();
    }

    // ---- pooled = accum / denom ----
    if (tid < 64)
        s.poolred[tid] = (s.part[0][tid] + s.part[1][tid] + s.part[2][tid] + s.part[3][tid])
                       * (1.f / s.red[2]);
    __syncthreads();

    // ---- write feature row ----
    if (tid < CONCAT) {
        float v;
        if      (tid < 64)  v = userE[(long)uid[b] * 64 + tid];
        else if (tid < 128) v = s.ibuf[tid - 64];
        else if (tid < 144) v = catE[(long)cid[b] * 16 + (tid - 128)];
        else if (tid < 152) v = durE[(long)did[b] * 8 + (tid - 144)];
        else if (tid < 177) v = udense[(long)b * 25 + (tid - 152)];
        else if (tid < 180) v = idense[(long)b * 3 + (tid - 177)];
        else                v = s.poolred[tid - 180];
        Sout[(long)b * CONCAT + tid] = v;
    }
}

// ---------------------------------------------------------------------------
// Kernel 2: batched GEMM + bias + ReLU via raw mma.tf32 (no CVT), 4-stage
// cp.async pipeline.  Block tile 128x128, BK=16, 8 warps (2x4), warp 64x32.
// ---------------------------------------------------------------------------
#define TBM 128
#define TBN 128
#define TBK 16
#define NSTG 4
#define ALD 20       // conflict-free for the 8x4 a-fragment pattern
#define BLD 136

#define GEMM_SMEM ((NSTG * TBM * ALD + NSTG * TBK * BLD) * 4)

__global__ void __launch_bounds__(256, 2)
wgemm_bias_relu(const float* __restrict__ A, const float* __restrict__ Bw,
                const float* __restrict__ bias, float* __restrict__ C,
                int M, int N, int K,
                size_t sA, size_t sB, size_t sBias, size_t sC)
{
    extern __shared__ float smemf[];
    float* As = smemf;                       // NSTG * TBM * ALD
    float* Bs = smemf + NSTG * TBM * ALD;    // NSTG * TBK * BLD

    const int z = blockIdx.z;
    A += (size_t)z * sA; Bw += (size_t)z * sB;
    bias += (size_t)z * sBias; C += (size_t)z * sC;

    const int m0 = blockIdx.y * TBM;
    const int n0 = blockIdx.x * TBN;
    const int tid = threadIdx.x;
    const int lane = tid & 31;
    const int warp = tid >> 5;
    const int wr = warp >> 2;            // 0..1 -> 64 rows
    const int wc = warp & 3;             // 0..3 -> 32 cols
    const int qr = lane >> 2;            // 0..7
    const int qc = lane & 3;             // 0..3

    const int nk = (K + TBK - 1) / TBK;

    auto load_stage = [&](int st, int k0) {
        float* as = As + st * TBM * ALD;
        float* bs = Bs + st * TBK * BLD;
        // A tile 128x16: 512 float4, 2 per thread
        #pragma unroll
        for (int h = 0; h < 2; h++) {
            const int idx = tid + h * 256;
            const int row = idx >> 2;
            const int c4  = (idx & 3) * 4;
            const int k = k0 + c4;
            const int sz = (k + 4 <= K) ? 16 : ((k < K) ? (K - k) * 4 : 0);
            const float* src = A + (size_t)(m0 + row) * K + ((k < K) ? k : 0);
            cp_async16z(&as[row * ALD + c4], src, sz);
        }
        // B tile 16x128: 512 float4, 2 per thread
        #pragma unroll
        for (int h = 0; h < 2; h++) {
            const int idx = tid + h * 256;
            const int row = idx >> 5;
            const int c4  = (idx & 31) * 4;
            const int k = k0 + row;
            const int sz = (k < K) ? 16 : 0;
            const float* src = Bw + (size_t)((k < K) ? k : 0) * N + n0 + c4;
            cp_async16z(&bs[row * BLD + c4], src, sz);
        }
    };

    float acc[4][4][4];
    #pragma unroll
    for (int i = 0; i < 4; i++)
        #pragma unroll
        for (int j = 0; j < 4; j++)
            #pragma unroll
            for (int e = 0; e < 4; e++) acc[i][j][e] = 0.f;

    // prologue: fill NSTG-1 stages
    #pragma unroll
    for (int s0 = 0; s0 < NSTG - 1; s0++) {
        if (s0 < nk) load_stage(s0, s0 * TBK);
        cp_commit();
    }

    for (int kt = 0; kt < nk; kt++) {
        cp_wait<NSTG - 2>();
        __syncthreads();

        // issue stage kt+NSTG-1 (buffer of stage kt-1, reads done pre-sync)
        const int knext = kt + NSTG - 1;
        if (knext < nk) load_stage(knext % NSTG, knext * TBK);
        cp_commit();

        const float* as = As + (kt % NSTG) * TBM * ALD;
        const float* bs = Bs + (kt % NSTG) * TBK * BLD;

        #pragma unroll
        for (int ks = 0; ks < TBK / 8; ks++) {
            float a[4][4], bfr[4][2];
            #pragma unroll
            for (int mi = 0; mi < 4; mi++) {
                const float* ap = &as[(wr * 64 + mi * 16 + qr) * ALD + ks * 8 + qc];
                a[mi][0] = ap[0];
                a[mi][1] = ap[8 * ALD];
                a[mi][2] = ap[4];
                a[mi][3] = ap[8 * ALD + 4];
            }
            #pragma unroll
            for (int ni = 0; ni < 4; ni++) {
                const float* bp = &bs[(ks * 8 + qc) * BLD + wc * 32 + ni * 8 + qr];
                bfr[ni][0] = bp[0];
                bfr[ni][1] = bp[4 * BLD];
            }
            #pragma unroll
            for (int mi = 0; mi < 4; mi++)
                #pragma unroll
                for (int ni = 0; ni < 4; ni++)
                    mma_tf32(acc[mi][ni], a[mi], bfr[ni]);
        }
        __syncthreads();
    }

    // epilogue: bias + relu, direct to global (float2 per fragment row)
    #pragma unroll
    for (int mi = 0; mi < 4; mi++) {
        #pragma unroll
        for (int ni = 0; ni < 4; ni++) {
            const int gm = m0 + wr * 64 + mi * 16 + qr;
            const int gn = n0 + wc * 32 + ni * 8 + qc * 2;
            const float b0 = bias[gn], b1 = bias[gn + 1];
            float2 v0, v1;
            v0.x = fmaxf(acc[mi][ni][0] + b0, 0.f);
            v0.y = fmaxf(acc[mi][ni][1] + b1, 0.f);
            v1.x = fmaxf(acc[mi][ni][2] + b0, 0.f);
            v1.y = fmaxf(acc[mi][ni][3] + b1, 0.f);
            *reinterpret_cast<float2*>(C + (size_t)gm * N + gn) = v0;
            *reinterpret_cast<float2*>(C + (size_t)(gm + 8) * N + gn) = v1;
        }
    }
}

// ---------------------------------------------------------------------------
// Kernel 3: gates (softmax) + expert mix + towers + sigmoid
// ---------------------------------------------------------------------------
__global__ void __launch_bounds__(256)
head_kernel(const float* __restrict__ S, const float* __restrict__ eo,
            const float* __restrict__ gW, const float* __restrict__ gb,
            const float* __restrict__ tW1, const float* __restrict__ tb1,
            const float* __restrict__ tW2, const float* __restrict__ tb2,
            const float* __restrict__ tW3, const float* __restrict__ tb3,
            float* __restrict__ out)
{
    __shared__ float Srow[4][CONCAT];
    __shared__ float gate[4][16];
    __shared__ float ti[4][NTASK][EOUT];
    __shared__ float x1[4][NTASK][64];
    __shared__ float x2[4][NTASK][32];

    const int g = threadIdx.x >> 6;
    const int lane = threadIdx.x & 63;
    const int b = blockIdx.x * 4 + g;

    for (int c = lane; c < CONCAT; c += 64) Srow[g][c] = S[(long)b * CONCAT + c];
    __syncthreads();

    {
        const int o = lane >> 2;
        const int q = lane & 3;
        const int t = o >> 3, e = o & 7;
        const int c0 = q * 61;
        float acc = 0.f;
        #pragma unroll 8
        for (int c = c0; c < c0 + 61; c++)
            acc += Srow[g][c] * __ldg(&gW[((long)t * CONCAT + c) * 8 + e]);
        acc += __shfl_xor_sync(0xffffffffu, acc, 1);
        acc += __shfl_xor_sync(0xffffffffu, acc, 2);
        if (q == 0) gate[g][o] = acc + gb[t * 8 + e];
    }
    __syncthreads();
    if (lane < 2) {
        const int t = lane;
        float mx = -3.4e38f;
        for (int e = 0; e < 8; e++) mx = fmaxf(mx, gate[g][t * 8 + e]);
        float sum = 0.f, ex[8];
        for (int e = 0; e < 8; e++) { ex[e] = __expf(gate[g][t * 8 + e] - mx); sum += ex[e]; }
        const float is = 1.f / sum;
        for (int e = 0; e < 8; e++) gate[g][t * 8 + e] = ex[e] * is;
    }
    __syncthreads();

    {
        const int t = lane >> 5;
        const int o = (lane & 31) * 4;
        float4 acc = make_float4(0.f, 0.f, 0.f, 0.f);
        #pragma unroll
        for (int e = 0; e < 8; e++) {
            const float gv = gate[g][t * 8 + e];
            const float4 v = *reinterpret_cast<const float4*>(
                eo + ((long)e * BATCH + b) * EOUT + o);
            acc.x += gv * v.x; acc.y += gv * v.y;
            acc.z += gv * v.z; acc.w += gv * v.w;
        }
        *reinterpret_cast<float4*>(&ti[g][t][o]) = acc;
    }
    __syncthreads();

    for (int idx = lane; idx < NTASK * 64; idx += 64) {
        const int t = idx >> 6, j = idx & 63;
        float acc = tb1[t * 64 + j];
        #pragma unroll 8
        for (int o = 0; o < 128; o++)
            acc += ti[g][t][o] * __ldg(&tW1[((long)t * 128 + o) * 64 + j]);
        x1[g][t][j] = fmaxf(acc, 0.f);
    }
    __syncthreads();

    {
        const int t = lane >> 5, m = lane & 31;
        float acc = tb2[t * 32 + m];
        #pragma unroll 8
        for (int j = 0; j < 64; j++)
            acc += x1[g][t][j] * __ldg(&tW2[(t * 64 + j) * 32 + m]);
        x2[g][t][m] = fmaxf(acc, 0.f);
    }
    __syncthreads();

    if (lane < 2) {
        const int t = lane;
        float acc = tb3[t];
        #pragma unroll
        for (int m = 0; m < 32; m++) acc += x2[g][t][m] * tW3[t * 32 + m];
        out[(long)t * BATCH + b] = 1.f / (1.f + __expf(-acc));
    }
}

// ---------------------------------------------------------------------------
// Launch
// ---------------------------------------------------------------------------
extern "C" void kernel_launch(void* const* d_in, const int* in_sizes, int n_in,
                              void* d_out, int out_size)
{
    const int*   uid    = (const int*)  d_in[0];
    const int*   iid    = (const int*)  d_in[1];
    const int*   cid    = (const int*)  d_in[2];
    const int*   did    = (const int*)  d_in[3];
    const float* udense = (const float*)d_in[4];
    const float* idense = (const float*)d_in[5];
    const int*   hseq   = (const int*)  d_in[6];
    const float* userE  = (const float*)d_in[7];
    const float* itemE  = (const float*)d_in[8];
    const float* catE   = (const float*)d_in[9];
    const float* durE   = (const float*)d_in[10];
    const float* histE  = (const float*)d_in[11];
    const float* Wproj  = (const float*)d_in[12];
    const float* aW1    = (const float*)d_in[13];
    const float* ab1    = (const float*)d_in[14];
    const float* aW2    = (const float*)d_in[15];
    const float* ab2    = (const float*)d_in[16];
    const float* aW3    = (const float*)d_in[17];
    const float* ab3    = (const float*)d_in[18];
    const float* eW1    = (const float*)d_in[19];
    const float* eb1    = (const float*)d_in[20];
    const float* eW2    = (const float*)d_in[21];
    const float* eb2    = (const float*)d_in[22];
    const float* gW     = (const float*)d_in[23];
    const float* gb     = (const float*)d_in[24];
    const float* tW1    = (const float*)d_in[25];
    const float* tb1    = (const float*)d_in[26];
    const float* tW2    = (const float*)d_in[27];
    const float* tb2    = (const float*)d_in[28];
    const float* tW3    = (const float*)d_in[29];
    const float* tb3    = (const float*)d_in[30];
    float* out = (float*)d_out;

    float *pS, *pEh, *pEo;
    cudaGetSymbolAddress((void**)&pS,  g_S);
    cudaGetSymbolAddress((void**)&pEh, g_eh);
    cudaGetSymbolAddress((void**)&pEo, g_eo);

    const int attn_smem = (int)sizeof(AttnSmem);
    cudaFuncSetAttribute(attn_kernel, cudaFuncAttributeMaxDynamicSharedMemorySize, attn_smem);
    cudaFuncSetAttribute(wgemm_bias_relu, cudaFuncAttributeMaxDynamicSharedMemorySize, GEMM_SMEM);

    // K1: attention + feature concat
    attn_kernel<<<BATCH, 256, attn_smem>>>(
        uid, iid, cid, did, udense, idense, hseq,
        userE, itemE, catE, durE, histE, Wproj,
        aW1, ab1, aW2, ab2, aW3, ab3, pS);

    // K2a: eh = relu(S @ eW1 + eb1)  per expert
    wgemm_bias_relu<<<dim3(EHID / TBN, BATCH / TBM, NEXP), 256, GEMM_SMEM>>>(
        pS, eW1, eb1, pEh,
        BATCH, EHID, CONCAT,
        (size_t)0, (size_t)CONCAT * EHID, (size_t)EHID, (size_t)BATCH * EHID);

    // K2b: eo = relu(eh @ eW2 + eb2)  per expert
    wgemm_bias_relu<<<dim3(EOUT / TBN, BATCH / TBM, NEXP), 256, GEMM_SMEM>>>(
        pEh, eW2, eb2, pEo,
        BATCH, EOUT, EHID,
        (size_t)BATCH * EHID, (size_t)EHID * EOUT, (size_t)EOUT, (size_t)BATCH * EOUT);

    // K3: gates + mix + towers + sigmoid
    head_kernel<<<BATCH / 4, 256>>>(
        pS, pEo, gW, gb, tW1, tb1, tW2, tb2, tW3, tb3, out);
}

// round 6
// speedup vs baseline: 1.6339x; 1.0122x over previous
#include <cuda_runtime.h>
#include <cuda_bf16.h>
#include <math.h>

// ---------------------------------------------------------------------------
// Problem constants
// ---------------------------------------------------------------------------
#define BATCH   16384
#define LSEQ    200
#define CONCAT  244
#define NEXP    8
#define EHID    256
#define EOUT    128
#define NTASK   2
#define CHUNK   64
#define GLD     68     // gather/h1 leading dim (4*qr+qc conflict-free)
#define MLD     72     // M leading dim (8*qc+qr conflict-free)
#define WLD     24     // aW2 leading dim

// ---------------------------------------------------------------------------
// Scratch (static device globals — no allocation allowed)
// ---------------------------------------------------------------------------
__device__ float g_S [(long)BATCH * CONCAT];
__device__ float g_eh[(long)NEXP * BATCH * EHID];
__device__ float g_eo[(long)NEXP * BATCH * EOUT];

// ---------------------------------------------------------------------------
// cp.async helpers
// ---------------------------------------------------------------------------
__device__ __forceinline__ void cp_async16(void* smem_dst, const void* gsrc) {
    unsigned sm = (unsigned)__cvta_generic_to_shared(smem_dst);
    asm volatile("cp.async.cg.shared.global [%0], [%1], 16;\n" :: "r"(sm), "l"(gsrc));
}
__device__ __forceinline__ void cp_async16z(void* smem_dst, const void* gsrc, int srcbytes) {
    unsigned sm = (unsigned)__cvta_generic_to_shared(smem_dst);
    asm volatile("cp.async.cg.shared.global [%0], [%1], 16, %2;\n"
                 :: "r"(sm), "l"(gsrc), "r"(srcbytes));
}
__device__ __forceinline__ void cp_commit() {
    asm volatile("cp.async.commit_group;\n");
}
template <int N>
__device__ __forceinline__ void cp_wait() {
    asm volatile("cp.async.wait_group %0;\n" :: "n"(N));
}

// raw tf32 mma: D += A(16x8,row) * B(8x8,col); operands are fp32 bit patterns
// layouts (lane = 4*qr + qc, qr=lane>>2, qc=lane&3):
//   A: a0=A[qr][qc] a1=A[qr+8][qc] a2=A[qr][qc+4] a3=A[qr+8][qc+4]
//   B: b0=B[qc][qr] b1=B[qc+4][qr]
//   C: c0=C[qr][2qc] c1=C[qr][2qc+1] c2=C[qr+8][2qc] c3=C[qr+8][2qc+1]
__device__ __forceinline__ void mma_tf32(float* d, const float* a, const float* b) {
    asm volatile(
        "mma.sync.aligned.m16n8k8.row.col.f32.tf32.tf32.f32 "
        "{%0,%1,%2,%3}, {%4,%5,%6,%7}, {%8,%9}, {%0,%1,%2,%3};\n"
        : "+f"(d[0]), "+f"(d[1]), "+f"(d[2]), "+f"(d[3])
        : "r"(__float_as_uint(a[0])), "r"(__float_as_uint(a[1])),
          "r"(__float_as_uint(a[2])), "r"(__float_as_uint(a[3])),
          "r"(__float_as_uint(b[0])), "r"(__float_as_uint(b[1])));
}

// ---------------------------------------------------------------------------
// Kernel 1: DIN attention + fused online pooling + feature concat
// One block per batch row, 256 threads (8 warps), dynamic smem (~98 KB).
// Raw mma everywhere; bias folded via accumulator init; layer3 in registers.
// ---------------------------------------------------------------------------
struct AttnSmem {
    float gb[3][CHUNK * GLD];    // triple-buffered gathered history (52.2 KB)
    float h1[CHUNK * GLD];       // layer1 activations (17.4 KB)
    float M[64 * MLD];           // per-row combined layer1 matrix (18.4 KB)
    float aW2s[64 * WLD];        // staged aW2 (6.1 KB)
    float part[4][64];           // matvec partials / pooling partials
    float ibuf[64];
    float tvec[64];
    float base[64];              // ab1 + t @ (W0+W2)
    float poolred[64];
    float sc[CHUNK];             // chunk exp-weights
    float aW3s[16];
    float ab2s[16];
    float red[8];
    float denom;
    int   seqs[LSEQ];
};

__global__ void __launch_bounds__(256)
attn_kernel(const int* __restrict__ uid, const int* __restrict__ iid,
            const int* __restrict__ cid, const int* __restrict__ did,
            const float* __restrict__ udense, const float* __restrict__ idense,
            const int* __restrict__ hseq,
            const float* __restrict__ userE, const float* __restrict__ itemE,
            const float* __restrict__ catE,  const float* __restrict__ durE,
            const float* __restrict__ histE, const float* __restrict__ Wproj,
            const float* __restrict__ aW1, const float* __restrict__ ab1,
            const float* __restrict__ aW2, const float* __restrict__ ab2,
            const float* __restrict__ aW3, const float* __restrict__ ab3,
            float* __restrict__ Sout)
{
    extern __shared__ unsigned char smem_raw[];
    AttnSmem& s = *reinterpret_cast<AttnSmem*>(smem_raw);

    const int b    = blockIdx.x;
    const int tid  = threadIdx.x;
    const int lane = tid & 31;
    const int warp = tid >> 5;
    const int qr   = lane >> 2;
    const int qc   = lane & 3;

    // ---- stage constants + sequence ids ----
    const int item = iid[b];
    if (tid < 64) s.ibuf[tid] = itemE[(long)item * 64 + tid];
    for (int i = tid; i < 64 * WLD; i += 256) {
        const int r = i / WLD, c = i - r * WLD;
        s.aW2s[i] = (c < 16) ? aW2[r * 16 + c] : 0.f;
    }
    if (tid < 16) { s.aW3s[tid] = aW3[tid]; s.ab2s[tid] = ab2[tid]; }
    for (int l = tid; l < LSEQ; l += 256) s.seqs[l] = hseq[(long)b * LSEQ + l];
    if (tid == 0) s.denom = 0.f;
    __syncthreads();

    // ---- issue gather of chunk 0 (overlaps with setup math) ----
    #pragma unroll
    for (int h = 0; h < 4; h++) {
        const int idx = tid + h * 256;
        const int row = idx >> 4;
        const int c4  = (idx & 15) * 4;
        cp_async16(&s.gb[0][row * GLD + c4], histE + (long)s.seqs[row] * 64 + c4);
    }
    cp_commit();

    // ---- tvec = i_emb @ Wproj (256-thread, 4-way K split) ----
    {
        const int j = tid & 63, q = tid >> 6;
        float acc = 0.f;
        #pragma unroll
        for (int k = q * 16; k < q * 16 + 16; k++)
            acc += s.ibuf[k] * Wproj[k * 64 + j];
        s.part[q][j] = acc;
    }
    __syncthreads();
    if (tid < 64)
        s.tvec[tid] = s.part[0][tid] + s.part[1][tid] + s.part[2][tid] + s.part[3][tid];
    __syncthreads();

    // ---- base + M ----
    if (tid < 64) {
        float acc = ab1[tid];
        #pragma unroll 4
        for (int k = 0; k < 64; k++)
            acc += s.tvec[k] * (aW1[k * 64 + tid] + aW1[(128 + k) * 64 + tid]);
        s.base[tid] = acc;
    }
    for (int idx = tid; idx < 64 * 64; idx += 256) {
        const int k = idx >> 6, j = idx & 63;
        s.M[k * MLD + j] = aW1[(64 + k) * 64 + j] - aW1[(128 + k) * 64 + j]
                         + s.tvec[k] * aW1[(192 + k) * 64 + j];
    }
    s.part[tid >> 6][tid & 63] = 0.f;   // re-zero for pooling accumulation
    __syncthreads();

    const float ab3v = ab3[0];

    // ---- chunk loop (4 chunks of 64 positions; triple-buffered gathers) ----
    for (int c = 0; c < 4; c++) {
        if (c < 3) {
            const int c0n = (c + 1) * CHUNK;
            float* dst = s.gb[(c + 1) % 3];
            #pragma unroll
            for (int h = 0; h < 4; h++) {
                const int idx = tid + h * 256;
                const int row = idx >> 4;
                const int c4  = (idx & 15) * 4;
                const int l = c0n + row;
                const int sid = (l < LSEQ) ? s.seqs[l] : 0;   // row 0 is zeros
                cp_async16(&dst[row * GLD + c4], histE + (long)sid * 64 + c4);
            }
            cp_commit();
            cp_wait<1>();
        } else {
            cp_wait<0>();
        }
        __syncthreads();

        const float* gbuf = s.gb[c % 3];

        // ---- layer 1: h1(64x64) = relu(h @ M + base), raw mma, all 8 warps
        {
            const int r   = warp & 3;           // row tile (16 rows)
            const int cpp = warp >> 2;          // col half (32 cols)
            const int rowA = (r * 16 + qr) * GLD;
            float acc1[4][4];
            #pragma unroll
            for (int ni = 0; ni < 4; ni++) {
                const int n0 = cpp * 32 + ni * 8;
                acc1[ni][0] = s.base[n0 + 2 * qc];
                acc1[ni][1] = s.base[n0 + 2 * qc + 1];
                acc1[ni][2] = acc1[ni][0];
                acc1[ni][3] = acc1[ni][1];
            }
            #pragma unroll
            for (int ks = 0; ks < 8; ks++) {
                float a[4];
                const float* ap = &gbuf[rowA + ks * 8 + qc];
                a[0] = ap[0];
                a[1] = ap[8 * GLD];
                a[2] = ap[4];
                a[3] = ap[8 * GLD + 4];
                #pragma unroll
                for (int ni = 0; ni < 4; ni++) {
                    float bv[2];
                    const float* bp = &s.M[(ks * 8 + qc) * MLD + cpp * 32 + ni * 8 + qr];
                    bv[0] = bp[0];
                    bv[1] = bp[4 * MLD];
                    mma_tf32(acc1[ni], a, bv);
                }
            }
            #pragma unroll
            for (int ni = 0; ni < 4; ni++) {
                const int n0 = cpp * 32 + ni * 8;
                float2 v0 = make_float2(fmaxf(acc1[ni][0], 0.f), fmaxf(acc1[ni][1], 0.f));
                float2 v1 = make_float2(fmaxf(acc1[ni][2], 0.f), fmaxf(acc1[ni][3], 0.f));
                *reinterpret_cast<float2*>(&s.h1[(r * 16 + qr) * GLD + n0 + 2 * qc]) = v0;
                *reinterpret_cast<float2*>(&s.h1[(r * 16 + qr + 8) * GLD + n0 + 2 * qc]) = v1;
            }
        }
        __syncthreads();

        // ---- layer 2 (mma) + layer 3 (registers) : warps 0-3 ----
        if (warp < 4) {
            float acc2[2][4];
            #pragma unroll
            for (int ni = 0; ni < 2; ni++) {
                acc2[ni][0] = s.ab2s[ni * 8 + 2 * qc];
                acc2[ni][1] = s.ab2s[ni * 8 + 2 * qc + 1];
                acc2[ni][2] = acc2[ni][0];
                acc2[ni][3] = acc2[ni][1];
            }
            const int rowA = (warp * 16 + qr) * GLD;
            #pragma unroll
            for (int ks = 0; ks < 8; ks++) {
                float a[4];
                const float* ap = &s.h1[rowA + ks * 8 + qc];
                a[0] = ap[0];
                a[1] = ap[8 * GLD];
                a[2] = ap[4];
                a[3] = ap[8 * GLD + 4];
                #pragma unroll
                for (int ni = 0; ni < 2; ni++) {
                    float bv[2];
                    const float* bp = &s.aW2s[(ks * 8 + qc) * WLD + ni * 8 + qr];
                    bv[0] = bp[0];
                    bv[1] = bp[4 * WLD];
                    mma_tf32(acc2[ni], a, bv);
                }
            }
            // layer 3: score = sum_m relu(h2[m]) * aW3[m]
            float w0 = 0.f, w1 = 0.f;
            #pragma unroll
            for (int ni = 0; ni < 2; ni++) {
                const float g0 = s.aW3s[ni * 8 + 2 * qc];
                const float g1 = s.aW3s[ni * 8 + 2 * qc + 1];
                w0 += fmaxf(acc2[ni][0], 0.f) * g0 + fmaxf(acc2[ni][1], 0.f) * g1;
                w1 += fmaxf(acc2[ni][2], 0.f) * g0 + fmaxf(acc2[ni][3], 0.f) * g1;
            }
            w0 += __shfl_xor_sync(0xffffffffu, w0, 1);
            w0 += __shfl_xor_sync(0xffffffffu, w0, 2);
            w1 += __shfl_xor_sync(0xffffffffu, w1, 1);
            w1 += __shfl_xor_sync(0xffffffffu, w1, 2);
            float e0 = 0.f, e1 = 0.f;
            if (qc == 0) {
                const int l0 = c * CHUNK + warp * 16 + qr;
                const int l1 = l0 + 8;
                if (l0 < LSEQ && s.seqs[l0] != 0) e0 = __expf(w0 + ab3v);
                if (l1 < LSEQ && s.seqs[l1] != 0) e1 = __expf(w1 + ab3v);
                s.sc[warp * 16 + qr]     = e0;
                s.sc[warp * 16 + qr + 8] = e1;
            }
            float tot = e0 + e1;
            #pragma unroll
            for (int off = 16; off >= 1; off >>= 1)
                tot += __shfl_xor_sync(0xffffffffu, tot, off);
            if (lane == 0) s.red[warp] = tot;
        }
        __syncthreads();

        if (tid == 0) s.denom += s.red[0] + s.red[1] + s.red[2] + s.red[3];

        // ---- pooling accumulation: part[g][d] += sum_l w_l * h[l][d] ----
        {
            const int d = tid & 63, g = tid >> 6;
            float acc = s.part[g][d];
            #pragma unroll
            for (int i = 0; i < 16; i++) {
                const int l = g * 16 + i;
                acc += s.sc[l] * gbuf[l * GLD + d];
            }
            s.part[g][d] = acc;
        }
        // no trailing sync: next iteration gathers into a different buffer,
        // and its cp_wait+__syncthreads orders everything else
    }
    __syncthreads();

    // ---- pooled = accum / denom ----
    if (tid < 64)
        s.poolred[tid] = (s.part[0][tid] + s.part[1][tid] + s.part[2][tid] + s.part[3][tid])
                       * (1.f / s.denom);
    __syncthreads();

    // ---- write feature row ----
    if (tid < CONCAT) {
        float v;
        if      (tid < 64)  v = userE[(long)uid[b] * 64 + tid];
        else if (tid < 128) v = s.ibuf[tid - 64];
        else if (tid < 144) v = catE[(long)cid[b] * 16 + (tid - 128)];
        else if (tid < 152) v = durE[(long)did[b] * 8 + (tid - 144)];
        else if (tid < 177) v = udense[(long)b * 25 + (tid - 152)];
        else if (tid < 180) v = idense[(long)b * 3 + (tid - 177)];
        else                v = s.poolred[tid - 180];
        Sout[(long)b * CONCAT + tid] = v;
    }
}

// ---------------------------------------------------------------------------
// Kernel 2: batched GEMM + bias + ReLU via raw mma.tf32, 4-stage cp.async
// pipeline.  Block tile 128x128, BK=16, 8 warps (2x4), warp 64x32.
// ---------------------------------------------------------------------------
#define TBM 128
#define TBN 128
#define TBK 16
#define NSTG 4
#define ALD 20
#define BLD 136

#define GEMM_SMEM ((NSTG * TBM * ALD + NSTG * TBK * BLD) * 4)

__global__ void __launch_bounds__(256, 2)
wgemm_bias_relu(const float* __restrict__ A, const float* __restrict__ Bw,
                const float* __restrict__ bias, float* __restrict__ C,
                int M, int N, int K,
                size_t sA, size_t sB, size_t sBias, size_t sC)
{
    extern __shared__ float smemf[];
    float* As = smemf;
    float* Bs = smemf + NSTG * TBM * ALD;

    const int z = blockIdx.z;
    A += (size_t)z * sA; Bw += (size_t)z * sB;
    bias += (size_t)z * sBias; C += (size_t)z * sC;

    const int m0 = blockIdx.y * TBM;
    const int n0 = blockIdx.x * TBN;
    const int tid = threadIdx.x;
    const int lane = tid & 31;
    const int warp = tid >> 5;
    const int wr = warp >> 2;
    const int wc = warp & 3;
    const int qr = lane >> 2;
    const int qc = lane & 3;

    const int nk = (K + TBK - 1) / TBK;

    auto load_stage = [&](int st, int k0) {
        float* as = As + st * TBM * ALD;
        float* bs = Bs + st * TBK * BLD;
        #pragma unroll
        for (int h = 0; h < 2; h++) {
            const int idx = tid + h * 256;
            const int row = idx >> 2;
            const int c4  = (idx & 3) * 4;
            const int k = k0 + c4;
            const int sz = (k + 4 <= K) ? 16 : ((k < K) ? (K - k) * 4 : 0);
            const float* src = A + (size_t)(m0 + row) * K + ((k < K) ? k : 0);
            cp_async16z(&as[row * ALD + c4], src, sz);
        }
        #pragma unroll
        for (int h = 0; h < 2; h++) {
            const int idx = tid + h * 256;
            const int row = idx >> 5;
            const int c4  = (idx & 31) * 4;
            const int k = k0 + row;
            const int sz = (k < K) ? 16 : 0;
            const float* src = Bw + (size_t)((k < K) ? k : 0) * N + n0 + c4;
            cp_async16z(&bs[row * BLD + c4], src, sz);
        }
    };

    float acc[4][4][4];
    #pragma unroll
    for (int i = 0; i < 4; i++)
        #pragma unroll
        for (int j = 0; j < 4; j++)
            #pragma unroll
            for (int e = 0; e < 4; e++) acc[i][j][e] = 0.f;

    #pragma unroll
    for (int s0 = 0; s0 < NSTG - 1; s0++) {
        if (s0 < nk) load_stage(s0, s0 * TBK);
        cp_commit();
    }

    for (int kt = 0; kt < nk; kt++) {
        cp_wait<NSTG - 2>();
        __syncthreads();

        const int knext = kt + NSTG - 1;
        if (knext < nk) load_stage(knext % NSTG, knext * TBK);
        cp_commit();

        const float* as = As + (kt % NSTG) * TBM * ALD;
        const float* bs = Bs + (kt % NSTG) * TBK * BLD;

        #pragma unroll
        for (int ks = 0; ks < TBK / 8; ks++) {
            float a[4][4], bfr[4][2];
            #pragma unroll
            for (int mi = 0; mi < 4; mi++) {
                const float* ap = &as[(wr * 64 + mi * 16 + qr) * ALD + ks * 8 + qc];
                a[mi][0] = ap[0];
                a[mi][1] = ap[8 * ALD];
                a[mi][2] = ap[4];
                a[mi][3] = ap[8 * ALD + 4];
            }
            #pragma unroll
            for (int ni = 0; ni < 4; ni++) {
                const float* bp = &bs[(ks * 8 + qc) * BLD + wc * 32 + ni * 8 + qr];
                bfr[ni][0] = bp[0];
                bfr[ni][1] = bp[4 * BLD];
            }
            #pragma unroll
            for (int mi = 0; mi < 4; mi++)
                #pragma unroll
                for (int ni = 0; ni < 4; ni++)
                    mma_tf32(acc[mi][ni], a[mi], bfr[ni]);
        }
        __syncthreads();
    }

    #pragma unroll
    for (int mi = 0; mi < 4; mi++) {
        #pragma unroll
        for (int ni = 0; ni < 4; ni++) {
            const int gm = m0 + wr * 64 + mi * 16 + qr;
            const int gn = n0 + wc * 32 + ni * 8 + qc * 2;
            const float b0 = bias[gn], b1 = bias[gn + 1];
            float2 v0, v1;
            v0.x = fmaxf(acc[mi][ni][0] + b0, 0.f);
            v0.y = fmaxf(acc[mi][ni][1] + b1, 0.f);
            v1.x = fmaxf(acc[mi][ni][2] + b0, 0.f);
            v1.y = fmaxf(acc[mi][ni][3] + b1, 0.f);
            *reinterpret_cast<float2*>(C + (size_t)gm * N + gn) = v0;
            *reinterpret_cast<float2*>(C + (size_t)(gm + 8) * N + gn) = v1;
        }
    }
}

// ---------------------------------------------------------------------------
// Kernel 3: gates (softmax) + expert mix + towers + sigmoid
// ---------------------------------------------------------------------------
__global__ void __launch_bounds__(256)
head_kernel(const float* __restrict__ S, const float* __restrict__ eo,
            const float* __restrict__ gW, const float* __restrict__ gb,
            const float* __restrict__ tW1, const float* __restrict__ tb1,
            const float* __restrict__ tW2, const float* __restrict__ tb2,
            const float* __restrict__ tW3, const float* __restrict__ tb3,
            float* __restrict__ out)
{
    __shared__ float Srow[4][CONCAT];
    __shared__ float gate[4][16];
    __shared__ float ti[4][NTASK][EOUT];
    __shared__ float x1[4][NTASK][64];
    __shared__ float x2[4][NTASK][32];

    const int g = threadIdx.x >> 6;
    const int lane = threadIdx.x & 63;
    const int b = blockIdx.x * 4 + g;

    for (int c = lane; c < CONCAT; c += 64) Srow[g][c] = S[(long)b * CONCAT + c];
    __syncthreads();

    {
        const int o = lane >> 2;
        const int q = lane & 3;
        const int t = o >> 3, e = o & 7;
        const int c0 = q * 61;
        float acc = 0.f;
        #pragma unroll 8
        for (int c = c0; c < c0 + 61; c++)
            acc += Srow[g][c] * __ldg(&gW[((long)t * CONCAT + c) * 8 + e]);
        acc += __shfl_xor_sync(0xffffffffu, acc, 1);
        acc += __shfl_xor_sync(0xffffffffu, acc, 2);
        if (q == 0) gate[g][o] = acc + gb[t * 8 + e];
    }
    __syncthreads();
    if (lane < 2) {
        const int t = lane;
        float mx = -3.4e38f;
        for (int e = 0; e < 8; e++) mx = fmaxf(mx, gate[g][t * 8 + e]);
        float sum = 0.f, ex[8];
        for (int e = 0; e < 8; e++) { ex[e] = __expf(gate[g][t * 8 + e] - mx); sum += ex[e]; }
        const float is = 1.f / sum;
        for (int e = 0; e < 8; e++) gate[g][t * 8 + e] = ex[e] * is;
    }
    __syncthreads();

    {
        const int t = lane >> 5;
        const int o = (lane & 31) * 4;
        float4 acc = make_float4(0.f, 0.f, 0.f, 0.f);
        #pragma unroll
        for (int e = 0; e < 8; e++) {
            const float gv = gate[g][t * 8 + e];
            const float4 v = *reinterpret_cast<const float4*>(
                eo + ((long)e * BATCH + b) * EOUT + o);
            acc.x += gv * v.x; acc.y += gv * v.y;
            acc.z += gv * v.z; acc.w += gv * v.w;
        }
        *reinterpret_cast<float4*>(&ti[g][t][o]) = acc;
    }
    __syncthreads();

    for (int idx = lane; idx < NTASK * 64; idx += 64) {
        const int t = idx >> 6, j = idx & 63;
        float acc = tb1[t * 64 + j];
        #pragma unroll 8
        for (int o = 0; o < 128; o++)
            acc += ti[g][t][o] * __ldg(&tW1[((long)t * 128 + o) * 64 + j]);
        x1[g][t][j] = fmaxf(acc, 0.f);
    }
    __syncthreads();

    {
        const int t = lane >> 5, m = lane & 31;
        float acc = tb2[t * 32 + m];
        #pragma unroll 8
        for (int j = 0; j < 64; j++)
            acc += x1[g][t][j] * __ldg(&tW2[(t * 64 + j) * 32 + m]);
        x2[g][t][m] = fmaxf(acc, 0.f);
    }
    __syncthreads();

    if (lane < 2) {
        const int t = lane;
        float acc = tb3[t];
        #pragma unroll
        for (int m = 0; m < 32; m++) acc += x2[g][t][m] * tW3[t * 32 + m];
        out[(long)t * BATCH + b] = 1.f / (1.f + __expf(-acc));
    }
}

// ---------------------------------------------------------------------------
// Launch
// ---------------------------------------------------------------------------
extern "C" void kernel_launch(void* const* d_in, const int* in_sizes, int n_in,
                              void* d_out, int out_size)
{
    const int*   uid    = (const int*)  d_in[0];
    const int*   iid    = (const int*)  d_in[1];
    const int*   cid    = (const int*)  d_in[2];
    const int*   did    = (const int*)  d_in[3];
    const float* udense = (const float*)d_in[4];
    const float* idense = (const float*)d_in[5];
    const int*   hseq   = (const int*)  d_in[6];
    const float* userE  = (const float*)d_in[7];
    const float* itemE  = (const float*)d_in[8];
    const float* catE   = (const float*)d_in[9];
    const float* durE   = (const float*)d_in[10];
    const float* histE  = (const float*)d_in[11];
    const float* Wproj  = (const float*)d_in[12];
    const float* aW1    = (const float*)d_in[13];
    const float* ab1    = (const float*)d_in[14];
    const float* aW2    = (const float*)d_in[15];
    const float* ab2    = (const float*)d_in[16];
    const float* aW3    = (const float*)d_in[17];
    const float* ab3    = (const float*)d_in[18];
    const float* eW1    = (const float*)d_in[19];
    const float* eb1    = (const float*)d_in[20];
    const float* eW2    = (const float*)d_in[21];
    const float* eb2    = (const float*)d_in[22];
    const float* gW     = (const float*)d_in[23];
    const float* gb     = (const float*)d_in[24];
    const float* tW1    = (const float*)d_in[25];
    const float* tb1    = (const float*)d_in[26];
    const float* tW2    = (const float*)d_in[27];
    const float* tb2    = (const float*)d_in[28];
    const float* tW3    = (const float*)d_in[29];
    const float* tb3    = (const float*)d_in[30];
    float* out = (float*)d_out;

    float *pS, *pEh, *pEo;
    cudaGetSymbolAddress((void**)&pS,  g_S);
    cudaGetSymbolAddress((void**)&pEh, g_eh);
    cudaGetSymbolAddress((void**)&pEo, g_eo);

    const int attn_smem = (int)sizeof(AttnSmem);
    cudaFuncSetAttribute(attn_kernel, cudaFuncAttributeMaxDynamicSharedMemorySize, attn_smem);
    cudaFuncSetAttribute(wgemm_bias_relu, cudaFuncAttributeMaxDynamicSharedMemorySize, GEMM_SMEM);

    attn_kernel<<<BATCH, 256, attn_smem>>>(
        uid, iid, cid, did, udense, idense, hseq,
        userE, itemE, catE, durE, histE, Wproj,
        aW1, ab1, aW2, ab2, aW3, ab3, pS);

    wgemm_bias_relu<<<dim3(EHID / TBN, BATCH / TBM, NEXP), 256, GEMM_SMEM>>>(
        pS, eW1, eb1, pEh,
        BATCH, EHID, CONCAT,
        (size_t)0, (size_t)CONCAT * EHID, (size_t)EHID, (size_t)BATCH * EHID);

    wgemm_bias_relu<<<dim3(EOUT / TBN, BATCH / TBM, NEXP), 256, GEMM_SMEM>>>(
        pEh, eW2, eb2, pEo,
        BATCH, EOUT, EHID,
        (size_t)BATCH * EHID, (size_t)EHID * EOUT, (size_t)EOUT, (size_t)BATCH * EOUT);

    head_kernel<<<BATCH / 4, 256>>>(
        pS, pEo, gW, gb, tW1, tb1, tW2, tb2, tW3, tb3, out);
}

// round 7
// speedup vs baseline: 1.6942x; 1.0369x over previous
#include <cuda_runtime.h>
#include <cuda_fp16.h>
#include <math.h>

// ---------------------------------------------------------------------------
// Problem constants
// ---------------------------------------------------------------------------
#define BATCH   16384
#define LSEQ    200
#define CONCAT  244
#define KPAD    256    // padded K for fp16 GEMMs
#define NEXP    8
#define EHID    256
#define EOUT    128
#define NTASK   2
#define CHUNK   64
#define GLD     68     // K1 gather/h1 leading dim (fp32)
#define MLD     72     // K1 M leading dim
#define WLD     24     // K1 aW2 leading dim

// ---------------------------------------------------------------------------
// Scratch (static device globals — no allocation allowed)
// ---------------------------------------------------------------------------
__device__ float  g_S  [(long)BATCH * CONCAT];          // fp32 features (head)
__device__ __half g_Sh [(long)BATCH * KPAD];            // fp16 padded features (K2a)
__device__ __half g_ehh[(long)NEXP * BATCH * EHID];     // fp16 expert hidden
__device__ float  g_eo [(long)NEXP * BATCH * EOUT];     // fp32 expert out
__device__ __half g_W1t[(long)NEXP * EHID * KPAD];      // eW1 transposed [e][n][k]
__device__ __half g_W2t[(long)NEXP * EOUT * KPAD];      // eW2 transposed [e][n][k]

// ---------------------------------------------------------------------------
// cp.async helpers
// ---------------------------------------------------------------------------
__device__ __forceinline__ void cp_async16(void* smem_dst, const void* gsrc) {
    unsigned sm = (unsigned)__cvta_generic_to_shared(smem_dst);
    asm volatile("cp.async.cg.shared.global [%0], [%1], 16;\n" :: "r"(sm), "l"(gsrc));
}
__device__ __forceinline__ void cp_commit() {
    asm volatile("cp.async.commit_group;\n");
}
template <int N>
__device__ __forceinline__ void cp_wait() {
    asm volatile("cp.async.wait_group %0;\n" :: "n"(N));
}

// raw tf32 mma (K1): D += A(16x8,row) * B(8x8,col); fp32 bit patterns
__device__ __forceinline__ void mma_tf32(float* d, const float* a, const float* b) {
    asm volatile(
        "mma.sync.aligned.m16n8k8.row.col.f32.tf32.tf32.f32 "
        "{%0,%1,%2,%3}, {%4,%5,%6,%7}, {%8,%9}, {%0,%1,%2,%3};\n"
        : "+f"(d[0]), "+f"(d[1]), "+f"(d[2]), "+f"(d[3])
        : "r"(__float_as_uint(a[0])), "r"(__float_as_uint(a[1])),
          "r"(__float_as_uint(a[2])), "r"(__float_as_uint(a[3])),
          "r"(__float_as_uint(b[0])), "r"(__float_as_uint(b[1])));
}

// raw fp16 mma (K2): D += A(16x16,row) * B(16x8,col); packed half2 operands
//   A: a0={A[qr][2qc],A[qr][2qc+1]}  a1=rows+8  a2=cols+8  a3=both
//   B: b0={B[2qc][qr],B[2qc+1][qr]}  b1=k+8     (Bt[n][k] storage -> contiguous)
//   C: c0=C[qr][2qc] c1=C[qr][2qc+1] c2/c3=rows+8
__device__ __forceinline__ void mma_f16(float* d, const unsigned* a, const unsigned* b) {
    asm volatile(
        "mma.sync.aligned.m16n8k16.row.col.f32.f16.f16.f32 "
        "{%0,%1,%2,%3}, {%4,%5,%6,%7}, {%8,%9}, {%0,%1,%2,%3};\n"
        : "+f"(d[0]), "+f"(d[1]), "+f"(d[2]), "+f"(d[3])
        : "r"(a[0]), "r"(a[1]), "r"(a[2]), "r"(a[3]),
          "r"(b[0]), "r"(b[1]));
}

// ---------------------------------------------------------------------------
// Kernel 0: weight prep — transpose + fp16-convert expert weights (K padded)
// ---------------------------------------------------------------------------
__global__ void __launch_bounds__(256)
prep_weights(const float* __restrict__ eW1, const float* __restrict__ eW2,
             __half* __restrict__ W1t, __half* __restrict__ W2t)
{
    const int i = blockIdx.x * 256 + threadIdx.x;
    const int n1 = NEXP * EHID * KPAD;            // 524288
    if (i < n1) {
        const int e = i >> 16, n = (i >> 8) & 255, k = i & 255;
        const float v = (k < CONCAT) ? eW1[((long)e * CONCAT + k) * EHID + n] : 0.f;
        W1t[i] = __float2half(v);
    } else {
        const int j = i - n1;
        if (j < NEXP * EOUT * KPAD) {
            const int e = j >> 15, n = (j >> 8) & 127, k = j & 255;
            W2t[j] = __float2half(eW2[((long)e * EHID + k) * EOUT + n]);
        }
    }
}

// ---------------------------------------------------------------------------
// Kernel 1: DIN attention + fused online pooling + feature concat (tf32 mma)
// (unchanged from R6 except fp16 S copy in the epilogue)
// ---------------------------------------------------------------------------
struct AttnSmem {
    float gb[3][CHUNK * GLD];
    float h1[CHUNK * GLD];
    float M[64 * MLD];
    float aW2s[64 * WLD];
    float part[4][64];
    float ibuf[64];
    float tvec[64];
    float base[64];
    float poolred[64];
    float sc[CHUNK];
    float aW3s[16];
    float ab2s[16];
    float red[8];
    float denom;
    int   seqs[LSEQ];
};

__global__ void __launch_bounds__(256)
attn_kernel(const int* __restrict__ uid, const int* __restrict__ iid,
            const int* __restrict__ cid, const int* __restrict__ did,
            const float* __restrict__ udense, const float* __restrict__ idense,
            const int* __restrict__ hseq,
            const float* __restrict__ userE, const float* __restrict__ itemE,
            const float* __restrict__ catE,  const float* __restrict__ durE,
            const float* __restrict__ histE, const float* __restrict__ Wproj,
            const float* __restrict__ aW1, const float* __restrict__ ab1,
            const float* __restrict__ aW2, const float* __restrict__ ab2,
            const float* __restrict__ aW3, const float* __restrict__ ab3,
            float* __restrict__ Sout, __half* __restrict__ Shout)
{
    extern __shared__ unsigned char smem_raw[];
    AttnSmem& s = *reinterpret_cast<AttnSmem*>(smem_raw);

    const int b    = blockIdx.x;
    const int tid  = threadIdx.x;
    const int lane = tid & 31;
    const int warp = tid >> 5;
    const int qr   = lane >> 2;
    const int qc   = lane & 3;

    const int item = iid[b];
    if (tid < 64) s.ibuf[tid] = itemE[(long)item * 64 + tid];
    for (int i = tid; i < 64 * WLD; i += 256) {
        const int r = i / WLD, c = i - r * WLD;
        s.aW2s[i] = (c < 16) ? aW2[r * 16 + c] : 0.f;
    }
    if (tid < 16) { s.aW3s[tid] = aW3[tid]; s.ab2s[tid] = ab2[tid]; }
    for (int l = tid; l < LSEQ; l += 256) s.seqs[l] = hseq[(long)b * LSEQ + l];
    if (tid == 0) s.denom = 0.f;
    __syncthreads();

    #pragma unroll
    for (int h = 0; h < 4; h++) {
        const int idx = tid + h * 256;
        const int row = idx >> 4;
        const int c4  = (idx & 15) * 4;
        cp_async16(&s.gb[0][row * GLD + c4], histE + (long)s.seqs[row] * 64 + c4);
    }
    cp_commit();

    {
        const int j = tid & 63, q = tid >> 6;
        float acc = 0.f;
        #pragma unroll
        for (int k = q * 16; k < q * 16 + 16; k++)
            acc += s.ibuf[k] * Wproj[k * 64 + j];
        s.part[q][j] = acc;
    }
    __syncthreads();
    if (tid < 64)
        s.tvec[tid] = s.part[0][tid] + s.part[1][tid] + s.part[2][tid] + s.part[3][tid];
    __syncthreads();

    if (tid < 64) {
        float acc = ab1[tid];
        #pragma unroll 4
        for (int k = 0; k < 64; k++)
            acc += s.tvec[k] * (aW1[k * 64 + tid] + aW1[(128 + k) * 64 + tid]);
        s.base[tid] = acc;
    }
    for (int idx = tid; idx < 64 * 64; idx += 256) {
        const int k = idx >> 6, j = idx & 63;
        s.M[k * MLD + j] = aW1[(64 + k) * 64 + j] - aW1[(128 + k) * 64 + j]
                         + s.tvec[k] * aW1[(192 + k) * 64 + j];
    }
    s.part[tid >> 6][tid & 63] = 0.f;
    __syncthreads();

    const float ab3v = ab3[0];

    for (int c = 0; c < 4; c++) {
        if (c < 3) {
            const int c0n = (c + 1) * CHUNK;
            float* dst = s.gb[(c + 1) % 3];
            #pragma unroll
            for (int h = 0; h < 4; h++) {
                const int idx = tid + h * 256;
                const int row = idx >> 4;
                const int c4  = (idx & 15) * 4;
                const int l = c0n + row;
                const int sid = (l < LSEQ) ? s.seqs[l] : 0;
                cp_async16(&dst[row * GLD + c4], histE + (long)sid * 64 + c4);
            }
            cp_commit();
            cp_wait<1>();
        } else {
            cp_wait<0>();
        }
        __syncthreads();

        const float* gbuf = s.gb[c % 3];

        {
            const int r   = warp & 3;
            const int cpp = warp >> 2;
            const int rowA = (r * 16 + qr) * GLD;
            float acc1[4][4];
            #pragma unroll
            for (int ni = 0; ni < 4; ni++) {
                const int n0 = cpp * 32 + ni * 8;
                acc1[ni][0] = s.base[n0 + 2 * qc];
                acc1[ni][1] = s.base[n0 + 2 * qc + 1];
                acc1[ni][2] = acc1[ni][0];
                acc1[ni][3] = acc1[ni][1];
            }
            #pragma unroll
            for (int ks = 0; ks < 8; ks++) {
                float a[4];
                const float* ap = &gbuf[rowA + ks * 8 + qc];
                a[0] = ap[0];
                a[1] = ap[8 * GLD];
                a[2] = ap[4];
                a[3] = ap[8 * GLD + 4];
                #pragma unroll
                for (int ni = 0; ni < 4; ni++) {
                    float bv[2];
                    const float* bp = &s.M[(ks * 8 + qc) * MLD + cpp * 32 + ni * 8 + qr];
                    bv[0] = bp[0];
                    bv[1] = bp[4 * MLD];
                    mma_tf32(acc1[ni], a, bv);
                }
            }
            #pragma unroll
            for (int ni = 0; ni < 4; ni++) {
                const int n0 = cpp * 32 + ni * 8;
                float2 v0 = make_float2(fmaxf(acc1[ni][0], 0.f), fmaxf(acc1[ni][1], 0.f));
                float2 v1 = make_float2(fmaxf(acc1[ni][2], 0.f), fmaxf(acc1[ni][3], 0.f));
                *reinterpret_cast<float2*>(&s.h1[(r * 16 + qr) * GLD + n0 + 2 * qc]) = v0;
                *reinterpret_cast<float2*>(&s.h1[(r * 16 + qr + 8) * GLD + n0 + 2 * qc]) = v1;
            }
        }
        __syncthreads();

        if (warp < 4) {
            float acc2[2][4];
            #pragma unroll
            for (int ni = 0; ni < 2; ni++) {
                acc2[ni][0] = s.ab2s[ni * 8 + 2 * qc];
                acc2[ni][1] = s.ab2s[ni * 8 + 2 * qc + 1];
                acc2[ni][2] = acc2[ni][0];
                acc2[ni][3] = acc2[ni][1];
            }
            const int rowA = (warp * 16 + qr) * GLD;
            #pragma unroll
            for (int ks = 0; ks < 8; ks++) {
                float a[4];
                const float* ap = &s.h1[rowA + ks * 8 + qc];
                a[0] = ap[0];
                a[1] = ap[8 * GLD];
                a[2] = ap[4];
                a[3] = ap[8 * GLD + 4];
                #pragma unroll
                for (int ni = 0; ni < 2; ni++) {
                    float bv[2];
                    const float* bp = &s.aW2s[(ks * 8 + qc) * WLD + ni * 8 + qr];
                    bv[0] = bp[0];
                    bv[1] = bp[4 * WLD];
                    mma_tf32(acc2[ni], a, bv);
                }
            }
            float w0 = 0.f, w1 = 0.f;
            #pragma unroll
            for (int ni = 0; ni < 2; ni++) {
                const float g0 = s.aW3s[ni * 8 + 2 * qc];
                const float g1 = s.aW3s[ni * 8 + 2 * qc + 1];
                w0 += fmaxf(acc2[ni][0], 0.f) * g0 + fmaxf(acc2[ni][1], 0.f) * g1;
                w1 += fmaxf(acc2[ni][2], 0.f) * g0 + fmaxf(acc2[ni][3], 0.f) * g1;
            }
            w0 += __shfl_xor_sync(0xffffffffu, w0, 1);
            w0 += __shfl_xor_sync(0xffffffffu, w0, 2);
            w1 += __shfl_xor_sync(0xffffffffu, w1, 1);
            w1 += __shfl_xor_sync(0xffffffffu, w1, 2);
            float e0 = 0.f, e1 = 0.f;
            if (qc == 0) {
                const int l0 = c * CHUNK + warp * 16 + qr;
                const int l1 = l0 + 8;
                if (l0 < LSEQ && s.seqs[l0] != 0) e0 = __expf(w0 + ab3v);
                if (l1 < LSEQ && s.seqs[l1] != 0) e1 = __expf(w1 + ab3v);
                s.sc[warp * 16 + qr]     = e0;
                s.sc[warp * 16 + qr + 8] = e1;
            }
            float tot = e0 + e1;
            #pragma unroll
            for (int off = 16; off >= 1; off >>= 1)
                tot += __shfl_xor_sync(0xffffffffu, tot, off);
            if (lane == 0) s.red[warp] = tot;
        }
        __syncthreads();

        if (tid == 0) s.denom += s.red[0] + s.red[1] + s.red[2] + s.red[3];

        {
            const int d = tid & 63, g = tid >> 6;
            float acc = s.part[g][d];
            #pragma unroll
            for (int i = 0; i < 16; i++) {
                const int l = g * 16 + i;
                acc += s.sc[l] * gbuf[l * GLD + d];
            }
            s.part[g][d] = acc;
        }
    }
    __syncthreads();

    if (tid < 64)
        s.poolred[tid] = (s.part[0][tid] + s.part[1][tid] + s.part[2][tid] + s.part[3][tid])
                       * (1.f / s.denom);
    __syncthreads();

    {
        float v = 0.f;
        if (tid < CONCAT) {
            if      (tid < 64)  v = userE[(long)uid[b] * 64 + tid];
            else if (tid < 128) v = s.ibuf[tid - 64];
            else if (tid < 144) v = catE[(long)cid[b] * 16 + (tid - 128)];
            else if (tid < 152) v = durE[(long)did[b] * 8 + (tid - 144)];
            else if (tid < 177) v = udense[(long)b * 25 + (tid - 152)];
            else if (tid < 180) v = idense[(long)b * 3 + (tid - 177)];
            else                v = s.poolred[tid - 180];
            Sout[(long)b * CONCAT + tid] = v;
        }
        Shout[(long)b * KPAD + tid] = __float2half(v);   // fp16 padded copy
    }
}

// ---------------------------------------------------------------------------
// Kernel 2: batched fp16 GEMM + bias + ReLU (mma.m16n8k16), 4-stage cp.async.
// A [M][KPAD] fp16 row-major, Bt [N][KPAD] fp16 (transposed weights).
// Block tile 128x128, BK=16 halves, 8 warps (2x4), warp tile 64x32.
// ---------------------------------------------------------------------------
#define TBM 128
#define TBN 128
#define TBK 16
#define NSTG 4
#define HL  24       // halves per smem row (16 + 8 pad; bank-stride 12)

#define HGEMM_SMEM ((NSTG * TBM * HL + NSTG * TBN * HL) * 2)

template <bool OUT_HALF>
__global__ void __launch_bounds__(256, 2)
hgemm_bias_relu(const __half* __restrict__ A, const __half* __restrict__ Bt,
                const float* __restrict__ bias, void* __restrict__ Cout,
                int M, int N,
                size_t sA, size_t sB, size_t sBias, size_t sC)
{
    extern __shared__ __half smemh[];
    __half* As = smemh;                        // NSTG * TBM * HL
    __half* Bs = smemh + NSTG * TBM * HL;      // NSTG * TBN * HL

    const int z = blockIdx.z;
    A += (size_t)z * sA; Bt += (size_t)z * sB;
    bias += (size_t)z * sBias;

    const int m0 = blockIdx.y * TBM;
    const int n0 = blockIdx.x * TBN;
    const int tid = threadIdx.x;
    const int lane = tid & 31;
    const int warp = tid >> 5;
    const int wr = warp >> 2;            // 0..1 -> 64 rows
    const int wc = warp & 3;             // 0..3 -> 32 cols
    const int qr = lane >> 2;
    const int qc = lane & 3;

    const int nk = KPAD / TBK;           // 16

    const int l_row = tid >> 1;          // 0..127
    const int l_hc  = (tid & 1) * 8;     // half offset 0/8

    auto load_stage = [&](int st, int k0) {
        __half* as = As + st * TBM * HL;
        __half* bs = Bs + st * TBN * HL;
        cp_async16(&as[l_row * HL + l_hc], A  + (size_t)(m0 + l_row) * KPAD + k0 + l_hc);
        cp_async16(&bs[l_row * HL + l_hc], Bt + (size_t)(n0 + l_row) * KPAD + k0 + l_hc);
    };

    float acc[4][4][4];
    #pragma unroll
    for (int i = 0; i < 4; i++)
        #pragma unroll
        for (int j = 0; j < 4; j++)
            #pragma unroll
            for (int e = 0; e < 4; e++) acc[i][j][e] = 0.f;

    #pragma unroll
    for (int s0 = 0; s0 < NSTG - 1; s0++) {
        load_stage(s0, s0 * TBK);
        cp_commit();
    }

    for (int kt = 0; kt < nk; kt++) {
        cp_wait<NSTG - 2>();
        __syncthreads();

        const int knext = kt + NSTG - 1;
        if (knext < nk) load_stage(knext % NSTG, knext * TBK);
        cp_commit();

        const __half* as = As + (kt % NSTG) * TBM * HL;
        const __half* bs = Bs + (kt % NSTG) * TBN * HL;

        unsigned a[4][4], bfr[4][2];
        #pragma unroll
        for (int mi = 0; mi < 4; mi++) {
            const int r = wr * 64 + mi * 16 + qr;
            a[mi][0] = *reinterpret_cast<const unsigned*>(as + r * HL + 2 * qc);
            a[mi][1] = *reinterpret_cast<const unsigned*>(as + (r + 8) * HL + 2 * qc);
            a[mi][2] = *reinterpret_cast<const unsigned*>(as + r * HL + 2 * qc + 8);
            a[mi][3] = *reinterpret_cast<const unsigned*>(as + (r + 8) * HL + 2 * qc + 8);
        }
        #pragma unroll
        for (int ni = 0; ni < 4; ni++) {
            const int n = wc * 32 + ni * 8 + qr;
            bfr[ni][0] = *reinterpret_cast<const unsigned*>(bs + n * HL + 2 * qc);
            bfr[ni][1] = *reinterpret_cast<const unsigned*>(bs + n * HL + 2 * qc + 8);
        }
        #pragma unroll
        for (int mi = 0; mi < 4; mi++)
            #pragma unroll
            for (int ni = 0; ni < 4; ni++)
                mma_f16(acc[mi][ni], a[mi], bfr[ni]);

        __syncthreads();
    }

    // epilogue: bias + relu
    #pragma unroll
    for (int mi = 0; mi < 4; mi++) {
        #pragma unroll
        for (int ni = 0; ni < 4; ni++) {
            const int gm = m0 + wr * 64 + mi * 16 + qr;
            const int gn = n0 + wc * 32 + ni * 8 + qc * 2;
            const float b0 = bias[gn], b1 = bias[gn + 1];
            const float v0 = fmaxf(acc[mi][ni][0] + b0, 0.f);
            const float v1 = fmaxf(acc[mi][ni][1] + b1, 0.f);
            const float v2 = fmaxf(acc[mi][ni][2] + b0, 0.f);
            const float v3 = fmaxf(acc[mi][ni][3] + b1, 0.f);
            if (OUT_HALF) {
                __half* C = (__half*)Cout + (size_t)z * sC;
                *reinterpret_cast<__half2*>(C + (size_t)gm * N + gn) =
                    __floats2half2_rn(v0, v1);
                *reinterpret_cast<__half2*>(C + (size_t)(gm + 8) * N + gn) =
                    __floats2half2_rn(v2, v3);
            } else {
                float* C = (float*)Cout + (size_t)z * sC;
                *reinterpret_cast<float2*>(C + (size_t)gm * N + gn) = make_float2(v0, v1);
                *reinterpret_cast<float2*>(C + (size_t)(gm + 8) * N + gn) = make_float2(v2, v3);
            }
        }
    }
}

// ---------------------------------------------------------------------------
// Kernel 3: gates (softmax) + expert mix + towers + sigmoid
// ---------------------------------------------------------------------------
__global__ void __launch_bounds__(256)
head_kernel(const float* __restrict__ S, const float* __restrict__ eo,
            const float* __restrict__ gW, const float* __restrict__ gb,
            const float* __restrict__ tW1, const float* __restrict__ tb1,
            const float* __restrict__ tW2, const float* __restrict__ tb2,
            const float* __restrict__ tW3, const float* __restrict__ tb3,
            float* __restrict__ out)
{
    __shared__ float Srow[4][CONCAT];
    __shared__ float gate[4][16];
    __shared__ float ti[4][NTASK][EOUT];
    __shared__ float x1[4][NTASK][64];
    __shared__ float x2[4][NTASK][32];

    const int g = threadIdx.x >> 6;
    const int lane = threadIdx.x & 63;
    const int b = blockIdx.x * 4 + g;

    for (int c = lane; c < CONCAT; c += 64) Srow[g][c] = S[(long)b * CONCAT + c];
    __syncthreads();

    {
        const int o = lane >> 2;
        const int q = lane & 3;
        const int t = o >> 3, e = o & 7;
        const int c0 = q * 61;
        float acc = 0.f;
        #pragma unroll 8
        for (int c = c0; c < c0 + 61; c++)
            acc += Srow[g][c] * __ldg(&gW[((long)t * CONCAT + c) * 8 + e]);
        acc += __shfl_xor_sync(0xffffffffu, acc, 1);
        acc += __shfl_xor_sync(0xffffffffu, acc, 2);
        if (q == 0) gate[g][o] = acc + gb[t * 8 + e];
    }
    __syncthreads();
    if (lane < 2) {
        const int t = lane;
        float mx = -3.4e38f;
        for (int e = 0; e < 8; e++) mx = fmaxf(mx, gate[g][t * 8 + e]);
        float sum = 0.f, ex[8];
        for (int e = 0; e < 8; e++) { ex[e] = __expf(gate[g][t * 8 + e] - mx); sum += ex[e]; }
        const float is = 1.f / sum;
        for (int e = 0; e < 8; e++) gate[g][t * 8 + e] = ex[e] * is;
    }
    __syncthreads();

    {
        const int t = lane >> 5;
        const int o = (lane & 31) * 4;
        float4 acc = make_float4(0.f, 0.f, 0.f, 0.f);
        #pragma unroll
        for (int e = 0; e < 8; e++) {
            const float gv = gate[g][t * 8 + e];
            const float4 v = *reinterpret_cast<const float4*>(
                eo + ((long)e * BATCH + b) * EOUT + o);
            acc.x += gv * v.x; acc.y += gv * v.y;
            acc.z += gv * v.z; acc.w += gv * v.w;
        }
        *reinterpret_cast<float4*>(&ti[g][t][o]) = acc;
    }
    __syncthreads();

    for (int idx = lane; idx < NTASK * 64; idx += 64) {
        const int t = idx >> 6, j = idx & 63;
        float acc = tb1[t * 64 + j];
        #pragma unroll 8
        for (int o = 0; o < 128; o++)
            acc += ti[g][t][o] * __ldg(&tW1[((long)t * 128 + o) * 64 + j]);
        x1[g][t][j] = fmaxf(acc, 0.f);
    }
    __syncthreads();

    {
        const int t = lane >> 5, m = lane & 31;
        float acc = tb2[t * 32 + m];
        #pragma unroll 8
        for (int j = 0; j < 64; j++)
            acc += x1[g][t][j] * __ldg(&tW2[(t * 64 + j) * 32 + m]);
        x2[g][t][m] = fmaxf(acc, 0.f);
    }
    __syncthreads();

    if (lane < 2) {
        const int t = lane;
        float acc = tb3[t];
        #pragma unroll
        for (int m = 0; m < 32; m++) acc += x2[g][t][m] * tW3[t * 32 + m];
        out[(long)t * BATCH + b] = 1.f / (1.f + __expf(-acc));
    }
}

// ---------------------------------------------------------------------------
// Launch
// ---------------------------------------------------------------------------
extern "C" void kernel_launch(void* const* d_in, const int* in_sizes, int n_in,
                              void* d_out, int out_size)
{
    const int*   uid    = (const int*)  d_in[0];
    const int*   iid    = (const int*)  d_in[1];
    const int*   cid    = (const int*)  d_in[2];
    const int*   did    = (const int*)  d_in[3];
    const float* udense = (const float*)d_in[4];
    const float* idense = (const float*)d_in[5];
    const int*   hseq   = (const int*)  d_in[6];
    const float* userE  = (const float*)d_in[7];
    const float* itemE  = (const float*)d_in[8];
    const float* catE   = (const float*)d_in[9];
    const float* durE   = (const float*)d_in[10];
    const float* histE  = (const float*)d_in[11];
    const float* Wproj  = (const float*)d_in[12];
    const float* aW1    = (const float*)d_in[13];
    const float* ab1    = (const float*)d_in[14];
    const float* aW2    = (const float*)d_in[15];
    const float* ab2    = (const float*)d_in[16];
    const float* aW3    = (const float*)d_in[17];
    const float* ab3    = (const float*)d_in[18];
    const float* eW1    = (const float*)d_in[19];
    const float* eb1    = (const float*)d_in[20];
    const float* eW2    = (const float*)d_in[21];
    const float* eb2    = (const float*)d_in[22];
    const float* gW     = (const float*)d_in[23];
    const float* gb     = (const float*)d_in[24];
    const float* tW1    = (const float*)d_in[25];
    const float* tb1    = (const float*)d_in[26];
    const float* tW2    = (const float*)d_in[27];
    const float* tb2    = (const float*)d_in[28];
    const float* tW3    = (const float*)d_in[29];
    const float* tb3    = (const float*)d_in[30];
    float* out = (float*)d_out;

    float  *pS, *pEo;
    __half *pSh, *pEh, *pW1t, *pW2t;
    cudaGetSymbolAddress((void**)&pS,   g_S);
    cudaGetSymbolAddress((void**)&pSh,  g_Sh);
    cudaGetSymbolAddress((void**)&pEh,  g_ehh);
    cudaGetSymbolAddress((void**)&pEo,  g_eo);
    cudaGetSymbolAddress((void**)&pW1t, g_W1t);
    cudaGetSymbolAddress((void**)&pW2t, g_W2t);

    const int attn_smem = (int)sizeof(AttnSmem);
    cudaFuncSetAttribute(attn_kernel, cudaFuncAttributeMaxDynamicSharedMemorySize, attn_smem);
    cudaFuncSetAttribute(hgemm_bias_relu<true>,  cudaFuncAttributeMaxDynamicSharedMemorySize, HGEMM_SMEM);
    cudaFuncSetAttribute(hgemm_bias_relu<false>, cudaFuncAttributeMaxDynamicSharedMemorySize, HGEMM_SMEM);

    // K0: weight prep (fp16 transpose, K padded to 256)
    prep_weights<<<(NEXP * EHID * KPAD + NEXP * EOUT * KPAD) / 256, 256>>>(
        eW1, eW2, pW1t, pW2t);

    // K1: attention + feature concat (fp32 S + fp16 padded S)
    attn_kernel<<<BATCH, 256, attn_smem>>>(
        uid, iid, cid, did, udense, idense, hseq,
        userE, itemE, catE, durE, histE, Wproj,
        aW1, ab1, aW2, ab2, aW3, ab3, pS, pSh);

    // K2a: eh = relu(S @ eW1 + eb1), fp16 in/out (A shared across experts)
    hgemm_bias_relu<true><<<dim3(EHID / TBN, BATCH / TBM, NEXP), 256, HGEMM_SMEM>>>(
        pSh, pW1t, eb1, pEh,
        BATCH, EHID,
        (size_t)0, (size_t)EHID * KPAD, (size_t)EHID, (size_t)BATCH * EHID);

    // K2b: eo = relu(eh @ eW2 + eb2), fp16 in, fp32 out
    hgemm_bias_relu<false><<<dim3(EOUT / TBN, BATCH / TBM, NEXP), 256, HGEMM_SMEM>>>(
        pEh, pW2t, eb2, pEo,
        BATCH, EOUT,
        (size_t)BATCH * EHID, (size_t)EOUT * KPAD, (size_t)EOUT, (size_t)BATCH * EOUT);

    // K3: gates + mix + towers + sigmoid
    head_kernel<<<BATCH / 4, 256>>>(
        pS, pEo, gW, gb, tW1, tb1, tW2, tb2, tW3, tb3, out);
}